// round 1
// baseline (speedup 1.0000x reference)
#include <cuda_runtime.h>
#include <cuda_bf16.h>
#include <math.h>

// Problem constants
constexpr int B  = 2;
constexpr int T  = 8192;
constexpr int C  = 1024;
constexpr int H  = 16;
constexpr int BS = 64;
constexpr int LW = 128;
constexpr int D  = 64;          // C / H
constexpr int WN = BS + LW;     // 192 window size
constexpr int NB = T / BS;      // 128 blocks
constexpr int M  = B * T;       // 16384 rows for projections

// GEMM tiling
constexpr int BM = 128, BN = 128, BK = 16, TM = 8, TN = 8;

// Attention smem strides (padded for bank-conflict-free access)
constexpr int QS = D + 1;       // 65
constexpr int KSTR = D + 1;     // 65
constexpr int VSTR = D + 1;     // 65
constexpr int SSTR = WN + 1;    // 193
constexpr int SMEM_ATTN = (BS * QS + WN * KSTR + WN * VSTR + BS * SSTR) * (int)sizeof(float);

// Scratch (no cudaMalloc allowed)
__device__ __align__(16) float g_q[(size_t)M * C];
__device__ __align__(16) float g_k[(size_t)M * C];
__device__ __align__(16) float g_v[(size_t)M * C];
__device__ __align__(16) float g_a[(size_t)M * C];

// ---------------------------------------------------------------------------
// Y[m, n] = alpha * ( sum_k A[m,k] * Wt[n,k] + bias[n] )
// A: [M, C] row-major.  Wt: [C, C] row-major (output-channel major, so we use
// row n of Wt as the dot-product partner -> implements x @ W^T).
// ---------------------------------------------------------------------------
__global__ __launch_bounds__(256, 2)
void sgemm_bias(const float* __restrict__ A, const float* __restrict__ Wt,
                const float* __restrict__ bias, float* __restrict__ Y,
                float alpha)
{
    __shared__ float As[BK][BM + 4];
    __shared__ float Bs[BK][BN + 4];

    const int tid = threadIdx.x;
    const int bm  = blockIdx.y * BM;
    const int bn  = blockIdx.x * BN;
    const int tx  = tid & 15;   // n-direction (16)
    const int ty  = tid >> 4;   // m-direction (16)

    float acc[TM][TN] = {};

    const float* Aptr = A  + (size_t)bm * C;
    const float* Wptr = Wt + (size_t)bn * C;

    for (int k0 = 0; k0 < C; k0 += BK) {
        // Load 128x16 A tile and 128x16 W tile (512 float4 each, 2 per thread)
        #pragma unroll
        for (int i = 0; i < 2; i++) {
            const int c  = tid + i * 256;
            const int m  = c >> 2;
            const int kq = (c & 3) << 2;
            float4 va = *(const float4*)(Aptr + (size_t)m * C + k0 + kq);
            As[kq + 0][m] = va.x; As[kq + 1][m] = va.y;
            As[kq + 2][m] = va.z; As[kq + 3][m] = va.w;
            float4 vb = *(const float4*)(Wptr + (size_t)m * C + k0 + kq);
            Bs[kq + 0][m] = vb.x; Bs[kq + 1][m] = vb.y;
            Bs[kq + 2][m] = vb.z; Bs[kq + 3][m] = vb.w;
        }
        __syncthreads();

        #pragma unroll
        for (int k = 0; k < BK; k++) {
            float ra[TM], rb[TN];
            #pragma unroll
            for (int i = 0; i < TM; i++) ra[i] = As[k][ty * TM + i];
            #pragma unroll
            for (int j = 0; j < TN; j++) rb[j] = Bs[k][tx * TN + j];
            #pragma unroll
            for (int i = 0; i < TM; i++)
                #pragma unroll
                for (int j = 0; j < TN; j++)
                    acc[i][j] = fmaf(ra[i], rb[j], acc[i][j]);
        }
        __syncthreads();
    }

    #pragma unroll
    for (int i = 0; i < TM; i++) {
        const int m = bm + ty * TM + i;
        #pragma unroll
        for (int j = 0; j < TN; j += 4) {
            const int n = bn + tx * TN + j;
            float4 o;
            o.x = alpha * (acc[i][j + 0] + bias[n + 0]);
            o.y = alpha * (acc[i][j + 1] + bias[n + 1]);
            o.z = alpha * (acc[i][j + 2] + bias[n + 2]);
            o.w = alpha * (acc[i][j + 3] + bias[n + 3]);
            *(float4*)(Y + (size_t)m * C + n) = o;
        }
    }
}

// ---------------------------------------------------------------------------
// Block-local attention. One CTA per (block, head, batch).
// q,k,v,o are all [B, T, C] with the head laid out at column h*D.
// Window for block nb: global positions [start-64, start+128), clamped,
// out-of-range masked to -inf before softmax.
// ---------------------------------------------------------------------------
__global__ __launch_bounds__(256, 1)
void attn_kernel(const float* __restrict__ q, const float* __restrict__ k,
                 const float* __restrict__ v, float* __restrict__ o)
{
    extern __shared__ float sm[];
    float* Qs  = sm;                    // BS x QS
    float* Ksm = Qs  + BS * QS;         // WN x KSTR
    float* Vsm = Ksm + WN * KSTR;       // WN x VSTR
    float* Ssm = Vsm + WN * VSTR;       // BS x SSTR

    const int nb  = blockIdx.x;
    const int h   = blockIdx.y;
    const int b   = blockIdx.z;
    const int tid = threadIdx.x;
    const int start = nb * BS;
    const size_t rowBase = (size_t)b * T * C + (size_t)h * D;

    // Load Q block (64 x 64)
    for (int i = tid; i < BS * D; i += 256) {
        const int r = i >> 6, c = i & 63;
        Qs[r * QS + c] = q[rowBase + (size_t)(start + r) * C + c];
    }
    // Load K/V window (192 x 64), clamped indices (masked rows get prob 0)
    for (int i = tid; i < WN * D; i += 256) {
        const int r = i >> 6, c = i & 63;
        int p = start - LW / 2 + r;
        p = p < 0 ? 0 : (p >= T ? T - 1 : p);
        const size_t g = rowBase + (size_t)p * C + c;
        Ksm[r * KSTR + c] = k[g];
        Vsm[r * VSTR + c] = v[g];
    }
    __syncthreads();

    // Scores: S[qi][kj] = Q[qi,:] . K[kj,:]
    // thread (tx,ty): qi in {ty*4+i}, kj in {tx + 16*j}  (4x12 register tile)
    {
        const int tx = tid & 15, ty = tid >> 4;
        float accS[4][12] = {};
        #pragma unroll 4
        for (int d = 0; d < D; d++) {
            float qv[4], kv[12];
            #pragma unroll
            for (int i = 0; i < 4; i++) qv[i] = Qs[(ty * 4 + i) * QS + d];
            #pragma unroll
            for (int j = 0; j < 12; j++) kv[j] = Ksm[(tx + 16 * j) * KSTR + d];
            #pragma unroll
            for (int i = 0; i < 4; i++)
                #pragma unroll
                for (int j = 0; j < 12; j++)
                    accS[i][j] = fmaf(qv[i], kv[j], accS[i][j]);
        }
        #pragma unroll
        for (int i = 0; i < 4; i++)
            #pragma unroll
            for (int j = 0; j < 12; j++)
                Ssm[(ty * 4 + i) * SSTR + tx + 16 * j] = accS[i][j];
    }
    __syncthreads();

    // Softmax over kj with validity mask. One warp handles 8 rows.
    {
        const int lane = tid & 31, warp = tid >> 5;
        for (int r = warp; r < BS; r += 8) {
            float e[6];
            float mx = -INFINITY;
            #pragma unroll
            for (int t2 = 0; t2 < 6; t2++) {
                const int kj = lane + 32 * t2;
                const int p  = start - LW / 2 + kj;
                const float s = (p >= 0 && p < T) ? Ssm[r * SSTR + kj] : -INFINITY;
                e[t2] = s;
                mx = fmaxf(mx, s);
            }
            #pragma unroll
            for (int off = 16; off > 0; off >>= 1)
                mx = fmaxf(mx, __shfl_xor_sync(0xffffffffu, mx, off));
            float sum = 0.f;
            #pragma unroll
            for (int t2 = 0; t2 < 6; t2++) {
                const float ev = (e[t2] == -INFINITY) ? 0.f : __expf(e[t2] - mx);
                e[t2] = ev;
                sum += ev;
            }
            #pragma unroll
            for (int off = 16; off > 0; off >>= 1)
                sum += __shfl_xor_sync(0xffffffffu, sum, off);
            const float inv = 1.f / sum;
            #pragma unroll
            for (int t2 = 0; t2 < 6; t2++)
                Ssm[r * SSTR + lane + 32 * t2] = e[t2] * inv;
        }
    }
    __syncthreads();

    // PV: out[qi][d] = sum_kj P[qi][kj] * V[kj][d]
    // thread (tx,ty): qi in {ty*4+i}, d in {tx + 16*j} (4x4 register tile)
    {
        const int tx = tid & 15, ty = tid >> 4;
        float accO[4][4] = {};
        #pragma unroll 4
        for (int kj = 0; kj < WN; kj++) {
            float pv[4], vv[4];
            #pragma unroll
            for (int i = 0; i < 4; i++) pv[i] = Ssm[(ty * 4 + i) * SSTR + kj];
            #pragma unroll
            for (int j = 0; j < 4; j++) vv[j] = Vsm[kj * VSTR + tx + 16 * j];
            #pragma unroll
            for (int i = 0; i < 4; i++)
                #pragma unroll
                for (int j = 0; j < 4; j++)
                    accO[i][j] = fmaf(pv[i], vv[j], accO[i][j]);
        }
        #pragma unroll
        for (int i = 0; i < 4; i++) {
            const int qi = ty * 4 + i;
            const size_t base = rowBase + (size_t)(start + qi) * C;
            #pragma unroll
            for (int j = 0; j < 4; j++)
                o[base + tx + 16 * j] = accO[i][j];
        }
    }
}

// ---------------------------------------------------------------------------
extern "C" void kernel_launch(void* const* d_in, const int* in_sizes, int n_in,
                              void* d_out, int out_size)
{
    const float* query = (const float*)d_in[0];
    const float* key   = (const float*)d_in[1];
    const float* value = (const float*)d_in[2];
    const float* Wq    = (const float*)d_in[3];
    const float* bq    = (const float*)d_in[4];
    const float* Wk    = (const float*)d_in[5];
    const float* bk    = (const float*)d_in[6];
    const float* Wv    = (const float*)d_in[7];
    const float* bv    = (const float*)d_in[8];
    const float* Wo    = (const float*)d_in[9];
    const float* bo    = (const float*)d_in[10];
    float* out = (float*)d_out;

    float *gq, *gk, *gv, *ga;
    cudaGetSymbolAddress((void**)&gq, g_q);
    cudaGetSymbolAddress((void**)&gk, g_k);
    cudaGetSymbolAddress((void**)&gv, g_v);
    cudaGetSymbolAddress((void**)&ga, g_a);

    cudaFuncSetAttribute(attn_kernel,
                         cudaFuncAttributeMaxDynamicSharedMemorySize, SMEM_ATTN);

    const dim3 gg(C / BN, M / BM);
    const float scale = 0.125f;  // D^-0.5 = 64^-0.5

    sgemm_bias<<<gg, 256>>>(query, Wq, bq, gq, scale);
    sgemm_bias<<<gg, 256>>>(key,   Wk, bk, gk, 1.0f);
    sgemm_bias<<<gg, 256>>>(value, Wv, bv, gv, 1.0f);

    attn_kernel<<<dim3(NB, H, B), 256, SMEM_ATTN>>>(gq, gk, gv, ga);

    sgemm_bias<<<gg, 256>>>(ga, Wo, bo, out, 1.0f);
}

// round 3
// speedup vs baseline: 2.8538x; 2.8538x over previous
#include <cuda_runtime.h>
#include <cuda_bf16.h>
#include <math.h>
#include <cstdint>

// ---------------------------------------------------------------------------
// Problem constants
// ---------------------------------------------------------------------------
constexpr int B  = 2;
constexpr int T  = 8192;
constexpr int C  = 1024;
constexpr int H  = 16;
constexpr int BS = 64;
constexpr int LW = 128;
constexpr int D  = 64;
constexpr int WN = BS + LW;     // 192
constexpr int NB = T / BS;      // 128
constexpr int M  = B * T;       // 16384

// ---------------------------------------------------------------------------
// GEMM config: mma.sync.m16n8k8 tf32, CTA tile 256x128x32, 8 warps (64x64 each)
// ---------------------------------------------------------------------------
constexpr int GBM = 256;
constexpr int GBN = 128;
constexpr int GBK = 32;
constexpr int NKT = C / GBK;               // 32 k-tiles
constexpr int AST = GBM * GBK * 4;         // 32768 B per A stage
constexpr int BST = GBN * GBK * 4;         // 16384 B per B stage
constexpr int SM_B_OFF  = 3 * AST;         // 98304
constexpr int SM_BIAS   = 3 * AST + 3 * BST;  // 147456
constexpr int SM_GEMM   = SM_BIAS + GBN * 4;  // 147968

// Attention smem (floats):
//   Qs   [64 x 64]   @ 0        (4096)
//   Ksm  [192 x 65]  @ 4096     (12480)
//   Vsm  [192 x 64]  @ 16576    (12288)   total 28864 floats = 115456 B
//   Ssm  [64 x 196]  overlays Qs+Ksm (12544 <= 16576)
constexpr int QS    = 64;
constexpr int KSTR  = 65;
constexpr int VSTR  = 64;
constexpr int SSTR  = 196;
constexpr int OFF_K = BS * QS;             // 4096
constexpr int OFF_V = OFF_K + WN * KSTR;   // 16576
constexpr int SMEM_ATTN = (OFF_V + WN * VSTR) * (int)sizeof(float);  // 115456

// ---------------------------------------------------------------------------
// Scratch (no cudaMalloc allowed)
// ---------------------------------------------------------------------------
__device__ __align__(16) float g_q[(size_t)M * C];
__device__ __align__(16) float g_k[(size_t)M * C];
__device__ __align__(16) float g_v[(size_t)M * C];
__device__ __align__(16) float g_a[(size_t)M * C];

// ---------------------------------------------------------------------------
// PTX helpers (non-arch-specific: valid on base sm_103 target)
// ---------------------------------------------------------------------------
__device__ __forceinline__ uint32_t smem_u32(const void* p) {
    uint32_t a;
    asm("{ .reg .u64 t; cvta.to.shared.u64 t, %1; cvt.u32.u64 %0, t; }" : "=r"(a) : "l"(p));
    return a;
}

#define CP_ASYNC16(dst, src) \
    asm volatile("cp.async.cg.shared.global [%0], [%1], 16;" :: "r"(dst), "l"(src) : "memory")
#define CP_COMMIT() asm volatile("cp.async.commit_group;" ::: "memory")
#define CP_WAIT(n)  asm volatile("cp.async.wait_group %0;" :: "n"(n) : "memory")

#define LDSM_X4(r, addr) \
    asm volatile("ldmatrix.sync.aligned.m8n8.x4.shared.b16 {%0,%1,%2,%3}, [%4];" \
        : "=r"((r)[0]), "=r"((r)[1]), "=r"((r)[2]), "=r"((r)[3]) : "r"(addr))

#define MMA_TF32(d, a, b0, b1) \
    asm volatile("mma.sync.aligned.m16n8k8.row.col.f32.tf32.tf32.f32 " \
        "{%0,%1,%2,%3}, {%4,%5,%6,%7}, {%8,%9}, {%0,%1,%2,%3};" \
        : "+f"((d)[0]), "+f"((d)[1]), "+f"((d)[2]), "+f"((d)[3]) \
        : "r"((a)[0]), "r"((a)[1]), "r"((a)[2]), "r"((a)[3]), "r"(b0), "r"(b1))

__device__ __forceinline__ uint32_t to_tf32(uint32_t x) {
    uint32_t y;
    asm("cvt.rna.tf32.f32 %0, %1;" : "=r"(y) : "f"(__uint_as_float(x)));
    return y;
}

// ---------------------------------------------------------------------------
// GEMM: Y[m,n] = alpha * (sum_k A[m,k] * Wt[n,k] + bias[n])
// fp32 in/out, tf32 tensor-core compute with rna rounding.
// ---------------------------------------------------------------------------
__global__ __launch_bounds__(256, 1)
void gemm_mma(const float* __restrict__ A, const float* __restrict__ Wt,
              const float* __restrict__ bias, float* __restrict__ Y, float alpha)
{
    extern __shared__ char smem[];
    const uint32_t sA = smem_u32(smem);
    const uint32_t sB = sA + SM_B_OFF;
    float* bsm = (float*)(smem + SM_BIAS);

    const int tid  = threadIdx.x;
    const int wid  = tid >> 5;
    const int lane = tid & 31;
    const int bm   = blockIdx.y * GBM;
    const int n0   = blockIdx.x * GBN;

    if (tid < GBN / 4)
        *(float4*)(bsm + tid * 4) = *(const float4*)(bias + n0 + tid * 4);

    // Stage loaders: rows are 128B (32 tf32), sw128 permutes 16B granules.
    auto loadA = [&](int slot, int kt) {
        const float* src = A + (size_t)bm * C + kt * GBK;
        const uint32_t base = sA + slot * AST;
        #pragma unroll
        for (int c = 0; c < 8; c++) {
            const int ci = tid + c * 256;
            const int r = ci >> 3, c16 = ci & 7;
            CP_ASYNC16(base + r * 128 + ((c16 * 16) ^ ((r & 7) * 16)),
                       src + (size_t)r * C + c16 * 4);
        }
    };
    auto loadB = [&](int slot, int kt) {
        const float* src = Wt + (size_t)n0 * C + kt * GBK;
        const uint32_t base = sB + slot * BST;
        #pragma unroll
        for (int c = 0; c < 4; c++) {
            const int ci = tid + c * 256;
            const int r = ci >> 3, c16 = ci & 7;
            CP_ASYNC16(base + r * 128 + ((c16 * 16) ^ ((r & 7) * 16)),
                       src + (size_t)r * C + c16 * 4);
        }
    };

    loadA(0, 0); loadB(0, 0); CP_COMMIT();
    loadA(1, 1); loadB(1, 1); CP_COMMIT();

    float acc[4][8][4];
    #pragma unroll
    for (int i = 0; i < 4; i++)
        #pragma unroll
        for (int j = 0; j < 8; j++)
            #pragma unroll
            for (int l = 0; l < 4; l++) acc[i][j][l] = 0.f;

    // ldmatrix per-lane addressing. Matrix q = lane>>3, row-in-matrix = lane&7.
    const int r8 = lane & 7;
    const int qa = lane >> 3;
    const int wm = (wid & 3) * 64;     // warp m offset in CTA tile
    const int wn = (wid >> 2) * 64;    // warp n offset
    // A: matrices (q&1 -> +8 rows, q>>1 -> k hi 16B)
    const uint32_t a_row  = wm + (qa & 1) * 8 + r8;     // + mt*16
    const uint32_t a_rb   = a_row * 128;
    const uint32_t a_ksel = (uint32_t)(qa >> 1) * 16;   // ^ r8*16, + ks*32
    // B: matrices (q>>1 -> +8 rows, q&1 -> k hi 16B)
    const uint32_t b_row  = wn + (qa >> 1) * 8 + r8;    // + p*16
    const uint32_t b_rb   = b_row * 128;
    const uint32_t b_ksel = (uint32_t)(qa & 1) * 16;
    const uint32_t xorp   = (uint32_t)r8 * 16;

    for (int kt = 0; kt < NKT; kt++) {
        if (kt < NKT - 2) { CP_WAIT(1); } else { CP_WAIT(0); }
        __syncthreads();
        if (kt + 2 < NKT) {
            const int s2 = (kt + 2) % 3;
            loadA(s2, kt + 2); loadB(s2, kt + 2); CP_COMMIT();
        }
        const int slot = kt % 3;
        const uint32_t aBase = sA + slot * AST + a_rb;
        const uint32_t bBase = sB + slot * BST + b_rb;

        #pragma unroll
        for (int ks = 0; ks < 4; ks++) {
            const uint32_t akoff = ((uint32_t)ks * 32 + a_ksel) ^ xorp;
            const uint32_t bkoff = ((uint32_t)ks * 32 + b_ksel) ^ xorp;
            uint32_t af[4][4], bf[4][4];
            #pragma unroll
            for (int mt = 0; mt < 4; mt++)
                LDSM_X4(af[mt], aBase + mt * (16 * 128) + akoff);
            #pragma unroll
            for (int p = 0; p < 4; p++)
                LDSM_X4(bf[p], bBase + p * (16 * 128) + bkoff);
            #pragma unroll
            for (int mt = 0; mt < 4; mt++)
                #pragma unroll
                for (int l = 0; l < 4; l++) af[mt][l] = to_tf32(af[mt][l]);
            #pragma unroll
            for (int p = 0; p < 4; p++)
                #pragma unroll
                for (int l = 0; l < 4; l++) bf[p][l] = to_tf32(bf[p][l]);
            #pragma unroll
            for (int mt = 0; mt < 4; mt++)
                #pragma unroll
                for (int p = 0; p < 4; p++) {
                    MMA_TF32(acc[mt][2 * p + 0], af[mt], bf[p][0], bf[p][1]);
                    MMA_TF32(acc[mt][2 * p + 1], af[mt], bf[p][2], bf[p][3]);
                }
        }
    }
    __syncthreads();

    // Epilogue: d0,d1 -> (row, col..col+1), d2,d3 -> (row+8, col..col+1)
    const int erow = bm + wm + (lane >> 2);
    const int ecol0 = wn + 2 * (lane & 3);
    #pragma unroll
    for (int mt = 0; mt < 4; mt++) {
        #pragma unroll
        for (int nt = 0; nt < 8; nt++) {
            const int col = ecol0 + nt * 8;
            const float b0 = bsm[col], b1 = bsm[col + 1];
            float2 lo, hi;
            lo.x = alpha * (acc[mt][nt][0] + b0);
            lo.y = alpha * (acc[mt][nt][1] + b1);
            hi.x = alpha * (acc[mt][nt][2] + b0);
            hi.y = alpha * (acc[mt][nt][3] + b1);
            *(float2*)(Y + (size_t)(erow + mt * 16)     * C + n0 + col) = lo;
            *(float2*)(Y + (size_t)(erow + mt * 16 + 8) * C + n0 + col) = hi;
        }
    }
}

// ---------------------------------------------------------------------------
// Block-local attention. One CTA per (block, head, batch). 2 CTAs/SM.
// S kept in registers through QK; S smem overlays dead Q+K region.
// ---------------------------------------------------------------------------
__global__ __launch_bounds__(256, 2)
void attn_kernel(const float* __restrict__ q, const float* __restrict__ k,
                 const float* __restrict__ v, float* __restrict__ o)
{
    extern __shared__ float sm[];
    float* Qs  = sm;                 // 64 x 64
    float* Ksm = sm + OFF_K;         // 192 x 65
    float* Vsm = sm + OFF_V;         // 192 x 64
    float* Ssm = sm;                 // 64 x 196 (overlays Qs+Ksm after QK)

    const int nb  = blockIdx.x;
    const int h   = blockIdx.y;
    const int b   = blockIdx.z;
    const int tid = threadIdx.x;
    const int start = nb * BS;
    const size_t rowBase = (size_t)b * T * C + (size_t)h * D;

    for (int i = tid; i < BS * D; i += 256) {
        const int r = i >> 6, c = i & 63;
        Qs[r * QS + c] = q[rowBase + (size_t)(start + r) * C + c];
    }
    for (int i = tid; i < WN * D; i += 256) {
        const int r = i >> 6, c = i & 63;
        int p = start - LW / 2 + r;
        p = p < 0 ? 0 : (p >= T ? T - 1 : p);
        const size_t g = rowBase + (size_t)p * C + c;
        Ksm[r * KSTR + c] = k[g];
        Vsm[r * VSTR + c] = v[g];
    }
    __syncthreads();

    const int tx = tid & 15, ty = tid >> 4;

    // QK^T into registers (4 q-rows x 12 k-cols per thread)
    float accS[4][12];
    #pragma unroll
    for (int i = 0; i < 4; i++)
        #pragma unroll
        for (int j = 0; j < 12; j++) accS[i][j] = 0.f;
    #pragma unroll 4
    for (int d = 0; d < D; d++) {
        float qv[4], kv[12];
        #pragma unroll
        for (int i = 0; i < 4; i++) qv[i] = Qs[(ty * 4 + i) * QS + d];
        #pragma unroll
        for (int j = 0; j < 12; j++) kv[j] = Ksm[(tx + 16 * j) * KSTR + d];
        #pragma unroll
        for (int i = 0; i < 4; i++)
            #pragma unroll
            for (int j = 0; j < 12; j++)
                accS[i][j] = fmaf(qv[i], kv[j], accS[i][j]);
    }
    __syncthreads();   // all Q/K reads done; safe to overlay S

    #pragma unroll
    for (int i = 0; i < 4; i++)
        #pragma unroll
        for (int j = 0; j < 12; j++)
            Ssm[(ty * 4 + i) * SSTR + tx + 16 * j] = accS[i][j];
    __syncthreads();

    // Masked softmax (one warp per 8 rows round-robin)
    {
        const int lane = tid & 31, warp = tid >> 5;
        for (int r = warp; r < BS; r += 8) {
            float e[6];
            float mx = -INFINITY;
            #pragma unroll
            for (int t2 = 0; t2 < 6; t2++) {
                const int kj = lane + 32 * t2;
                const int p  = start - LW / 2 + kj;
                const float s = (p >= 0 && p < T) ? Ssm[r * SSTR + kj] : -INFINITY;
                e[t2] = s;
                mx = fmaxf(mx, s);
            }
            #pragma unroll
            for (int off = 16; off > 0; off >>= 1)
                mx = fmaxf(mx, __shfl_xor_sync(0xffffffffu, mx, off));
            float sum = 0.f;
            #pragma unroll
            for (int t2 = 0; t2 < 6; t2++) {
                const float ev = (e[t2] == -INFINITY) ? 0.f : __expf(e[t2] - mx);
                e[t2] = ev;
                sum += ev;
            }
            #pragma unroll
            for (int off = 16; off > 0; off >>= 1)
                sum += __shfl_xor_sync(0xffffffffu, sum, off);
            const float inv = 1.f / sum;
            #pragma unroll
            for (int t2 = 0; t2 < 6; t2++)
                Ssm[r * SSTR + lane + 32 * t2] = e[t2] * inv;
        }
    }
    __syncthreads();

    // P @ V (4 q-rows x 4 d-cols per thread)
    {
        float accO[4][4];
        #pragma unroll
        for (int i = 0; i < 4; i++)
            #pragma unroll
            for (int j = 0; j < 4; j++) accO[i][j] = 0.f;
        #pragma unroll 4
        for (int kj = 0; kj < WN; kj++) {
            float pv[4], vv[4];
            #pragma unroll
            for (int i = 0; i < 4; i++) pv[i] = Ssm[(ty * 4 + i) * SSTR + kj];
            #pragma unroll
            for (int j = 0; j < 4; j++) vv[j] = Vsm[kj * VSTR + tx + 16 * j];
            #pragma unroll
            for (int i = 0; i < 4; i++)
                #pragma unroll
                for (int j = 0; j < 4; j++)
                    accO[i][j] = fmaf(pv[i], vv[j], accO[i][j]);
        }
        #pragma unroll
        for (int i = 0; i < 4; i++) {
            const int qi = ty * 4 + i;
            const size_t base = rowBase + (size_t)(start + qi) * C;
            #pragma unroll
            for (int j = 0; j < 4; j++)
                o[base + tx + 16 * j] = accO[i][j];
        }
    }
}

// ---------------------------------------------------------------------------
extern "C" void kernel_launch(void* const* d_in, const int* in_sizes, int n_in,
                              void* d_out, int out_size)
{
    const float* query = (const float*)d_in[0];
    const float* key   = (const float*)d_in[1];
    const float* value = (const float*)d_in[2];
    const float* Wq    = (const float*)d_in[3];
    const float* bq    = (const float*)d_in[4];
    const float* Wk    = (const float*)d_in[5];
    const float* bk    = (const float*)d_in[6];
    const float* Wv    = (const float*)d_in[7];
    const float* bv    = (const float*)d_in[8];
    const float* Wo    = (const float*)d_in[9];
    const float* bo    = (const float*)d_in[10];
    float* out = (float*)d_out;

    float *gq, *gk, *gv, *ga;
    cudaGetSymbolAddress((void**)&gq, g_q);
    cudaGetSymbolAddress((void**)&gk, g_k);
    cudaGetSymbolAddress((void**)&gv, g_v);
    cudaGetSymbolAddress((void**)&ga, g_a);

    cudaFuncSetAttribute(gemm_mma,
                         cudaFuncAttributeMaxDynamicSharedMemorySize, SM_GEMM);
    cudaFuncSetAttribute(attn_kernel,
                         cudaFuncAttributeMaxDynamicSharedMemorySize, SMEM_ATTN);

    const dim3 gg(C / GBN, M / GBM);   // (8, 64)
    const float scale = 0.125f;        // 64^-0.5

    gemm_mma<<<gg, 256, SM_GEMM>>>(query, Wq, bq, gq, scale);
    gemm_mma<<<gg, 256, SM_GEMM>>>(key,   Wk, bk, gk, 1.0f);
    gemm_mma<<<gg, 256, SM_GEMM>>>(value, Wv, bv, gv, 1.0f);

    attn_kernel<<<dim3(NB, H, B), 256, SMEM_ATTN>>>(gq, gk, gv, ga);

    gemm_mma<<<gg, 256, SM_GEMM>>>(ga, Wo, bo, out, 1.0f);
}

// round 4
// speedup vs baseline: 3.5209x; 1.2338x over previous
#include <cuda_runtime.h>
#include <cuda_bf16.h>
#include <math.h>
#include <cstdint>

// ---------------------------------------------------------------------------
// Problem constants
// ---------------------------------------------------------------------------
constexpr int B  = 2;
constexpr int T  = 8192;
constexpr int C  = 1024;
constexpr int H  = 16;
constexpr int BS = 64;
constexpr int LW = 128;
constexpr int D  = 64;
constexpr int WN = BS + LW;     // 192
constexpr int NB = T / BS;      // 128
constexpr int M  = B * T;       // 16384

// ---------------------------------------------------------------------------
// GEMM config: mma.sync m16n8k8 tf32, CTA tile 128x256x32, 8 warps (64x64)
// ---------------------------------------------------------------------------
constexpr int GBM = 128;
constexpr int GBN = 256;
constexpr int GBK = 32;
constexpr int NKT = C / GBK;                  // 32
constexpr int AST = GBM * GBK * 4;            // 16384
constexpr int BST = GBN * GBK * 4;            // 32768
constexpr int SM_B_OFF = 3 * AST;             // 49152
constexpr int SM_BIAS  = 3 * AST + 3 * BST;   // 147456
constexpr int SM_GEMM  = SM_BIAS + GBN * 4;   // 148480

// ---------------------------------------------------------------------------
// Attention smem layout (bytes)
//   Qpan: 2 panels x 64 rows x 128B   = 16384   @ 0
//   Kpan: 2 panels x 192 rows x 128B  = 49152   @ 16384
//   Vsm : 192 rows x 288B (72 floats) = 55296   @ 65536
//   Ppan: 6 panels x 64 rows x 128B   = 49152   @ 120832
//   Ssm (raw scores, 64 x 196 f32 = 50176) overlays Qpan+Kpan (65536)
// ---------------------------------------------------------------------------
constexpr int AOFF_K = 16384;
constexpr int AOFF_V = 65536;
constexpr int AOFF_P = 120832;
constexpr int SMEM_ATTN = AOFF_P + 6 * 64 * 128;   // 169984
constexpr int SSTR = 196;
constexpr int VSTRIDE_F = 72;                       // floats per V row (288B)

// ---------------------------------------------------------------------------
// Scratch
// ---------------------------------------------------------------------------
__device__ __align__(16) float g_q[(size_t)M * C];
__device__ __align__(16) float g_k[(size_t)M * C];
__device__ __align__(16) float g_v[(size_t)M * C];
__device__ __align__(16) float g_a[(size_t)M * C];

// ---------------------------------------------------------------------------
// PTX helpers (base sm_103-safe)
// ---------------------------------------------------------------------------
__device__ __forceinline__ uint32_t smem_u32(const void* p) {
    uint32_t a;
    asm("{ .reg .u64 t; cvta.to.shared.u64 t, %1; cvt.u32.u64 %0, t; }" : "=r"(a) : "l"(p));
    return a;
}

#define CP_ASYNC16(dst, src) \
    asm volatile("cp.async.cg.shared.global [%0], [%1], 16;" :: "r"(dst), "l"(src) : "memory")
#define CP_COMMIT() asm volatile("cp.async.commit_group;" ::: "memory")
#define CP_WAIT(n)  asm volatile("cp.async.wait_group %0;" :: "n"(n) : "memory")

#define LDSM_X4(r, addr) \
    asm volatile("ldmatrix.sync.aligned.m8n8.x4.shared.b16 {%0,%1,%2,%3}, [%4];" \
        : "=r"((r)[0]), "=r"((r)[1]), "=r"((r)[2]), "=r"((r)[3]) : "r"(addr))

#define MMA_TF32(d, a, b0, b1) \
    asm volatile("mma.sync.aligned.m16n8k8.row.col.f32.tf32.tf32.f32 " \
        "{%0,%1,%2,%3}, {%4,%5,%6,%7}, {%8,%9}, {%0,%1,%2,%3};" \
        : "+f"((d)[0]), "+f"((d)[1]), "+f"((d)[2]), "+f"((d)[3]) \
        : "r"((a)[0]), "r"((a)[1]), "r"((a)[2]), "r"((a)[3]), "r"(b0), "r"(b1))

__device__ __forceinline__ uint32_t to_tf32(uint32_t x) {
    uint32_t y;
    asm("cvt.rna.tf32.f32 %0, %1;" : "=r"(y) : "f"(__uint_as_float(x)));
    return y;
}
__device__ __forceinline__ uint32_t f_to_tf32(float x) {
    uint32_t y;
    asm("cvt.rna.tf32.f32 %0, %1;" : "=r"(y) : "f"(x));
    return y;
}

// ---------------------------------------------------------------------------
// GEMM: Y[m,n] = alpha * (sum_k A[m,k] * Wt[n,k] + bias[n])
// ---------------------------------------------------------------------------
__global__ __launch_bounds__(256, 1)
void gemm_mma(const float* __restrict__ A, const float* __restrict__ Wt,
              const float* __restrict__ bias, float* __restrict__ Y, float alpha)
{
    extern __shared__ char smem[];
    const uint32_t sA = smem_u32(smem);
    const uint32_t sB = sA + SM_B_OFF;
    float* bsm = (float*)(smem + SM_BIAS);

    const int tid  = threadIdx.x;
    const int wid  = tid >> 5;
    const int lane = tid & 31;
    const int bm   = blockIdx.y * GBM;
    const int n0   = blockIdx.x * GBN;

    if (tid < GBN / 4)
        *(float4*)(bsm + tid * 4) = *(const float4*)(bias + n0 + tid * 4);

    auto loadA = [&](int slot, int kt) {
        const float* src = A + (size_t)bm * C + kt * GBK;
        const uint32_t base = sA + slot * AST;
        #pragma unroll
        for (int c = 0; c < 4; c++) {
            const int ci = tid + c * 256;
            const int r = ci >> 3, c16 = ci & 7;
            CP_ASYNC16(base + r * 128 + ((c16 * 16) ^ ((r & 7) * 16)),
                       src + (size_t)r * C + c16 * 4);
        }
    };
    auto loadB = [&](int slot, int kt) {
        const float* src = Wt + (size_t)n0 * C + kt * GBK;
        const uint32_t base = sB + slot * BST;
        #pragma unroll
        for (int c = 0; c < 8; c++) {
            const int ci = tid + c * 256;
            const int r = ci >> 3, c16 = ci & 7;
            CP_ASYNC16(base + r * 128 + ((c16 * 16) ^ ((r & 7) * 16)),
                       src + (size_t)r * C + c16 * 4);
        }
    };

    loadA(0, 0); loadB(0, 0); CP_COMMIT();
    loadA(1, 1); loadB(1, 1); CP_COMMIT();

    float acc[4][8][4];
    #pragma unroll
    for (int i = 0; i < 4; i++)
        #pragma unroll
        for (int j = 0; j < 8; j++)
            #pragma unroll
            for (int l = 0; l < 4; l++) acc[i][j][l] = 0.f;

    const int r8 = lane & 7;
    const int qa = lane >> 3;
    const int wm = (wid & 1) * 64;
    const int wn = (wid >> 1) * 64;
    const uint32_t a_rb   = (wm + (qa & 1) * 8 + r8) * 128;
    const uint32_t a_ksel = (uint32_t)(qa >> 1) * 16;
    const uint32_t b_rb   = (wn + (qa >> 1) * 8 + r8) * 128;
    const uint32_t b_ksel = (uint32_t)(qa & 1) * 16;
    const uint32_t xorp   = (uint32_t)r8 * 16;

    for (int kt = 0; kt < NKT; kt++) {
        if (kt < NKT - 2) { CP_WAIT(1); } else { CP_WAIT(0); }
        __syncthreads();
        if (kt + 2 < NKT) {
            const int s2 = (kt + 2) % 3;
            loadA(s2, kt + 2); loadB(s2, kt + 2); CP_COMMIT();
        }
        const int slot = kt % 3;
        const uint32_t aBase = sA + slot * AST + a_rb;
        const uint32_t bBase = sB + slot * BST + b_rb;

        #pragma unroll
        for (int ks = 0; ks < 4; ks++) {
            const uint32_t akoff = ((uint32_t)ks * 32 + a_ksel) ^ xorp;
            const uint32_t bkoff = ((uint32_t)ks * 32 + b_ksel) ^ xorp;
            uint32_t af[4][4], bf[4][4];
            #pragma unroll
            for (int mt = 0; mt < 4; mt++)
                LDSM_X4(af[mt], aBase + mt * (16 * 128) + akoff);
            #pragma unroll
            for (int p = 0; p < 4; p++)
                LDSM_X4(bf[p], bBase + p * (16 * 128) + bkoff);
            #pragma unroll
            for (int mt = 0; mt < 4; mt++)
                #pragma unroll
                for (int l = 0; l < 4; l++) af[mt][l] = to_tf32(af[mt][l]);
            #pragma unroll
            for (int p = 0; p < 4; p++)
                #pragma unroll
                for (int l = 0; l < 4; l++) bf[p][l] = to_tf32(bf[p][l]);
            #pragma unroll
            for (int mt = 0; mt < 4; mt++)
                #pragma unroll
                for (int p = 0; p < 4; p++) {
                    MMA_TF32(acc[mt][2 * p + 0], af[mt], bf[p][0], bf[p][1]);
                    MMA_TF32(acc[mt][2 * p + 1], af[mt], bf[p][2], bf[p][3]);
                }
        }
    }
    __syncthreads();

    const int erow  = bm + wm + (lane >> 2);
    const int ecol0 = wn + 2 * (lane & 3);
    #pragma unroll
    for (int mt = 0; mt < 4; mt++) {
        #pragma unroll
        for (int nt = 0; nt < 8; nt++) {
            const int col = ecol0 + nt * 8;
            const float b0 = bsm[col], b1 = bsm[col + 1];
            float2 lo, hi;
            lo.x = alpha * (acc[mt][nt][0] + b0);
            lo.y = alpha * (acc[mt][nt][1] + b1);
            hi.x = alpha * (acc[mt][nt][2] + b0);
            hi.y = alpha * (acc[mt][nt][3] + b1);
            *(float2*)(Y + (size_t)(erow + mt * 16)     * C + n0 + col) = lo;
            *(float2*)(Y + (size_t)(erow + mt * 16 + 8) * C + n0 + col) = hi;
        }
    }
}

// ---------------------------------------------------------------------------
// Tensor-core block-local attention. One CTA per (block, head, batch).
// QK: 8 warps 4x2 over 64x192. PV: 8 warps 4x2 over 64x64 (K=192).
// ---------------------------------------------------------------------------
__global__ __launch_bounds__(256, 1)
void attn_kernel(const float* __restrict__ q, const float* __restrict__ k,
                 const float* __restrict__ v, float* __restrict__ o)
{
    extern __shared__ char smem[];
    const uint32_t sb = smem_u32(smem);
    float* Ssm  = (float*)smem;                 // overlays Qpan+Kpan
    float* Vsm  = (float*)(smem + AOFF_V);
    float* Ppan = (float*)(smem + AOFF_P);

    const int nb  = blockIdx.x;
    const int h   = blockIdx.y;
    const int b   = blockIdx.z;
    const int tid = threadIdx.x;
    const int wid  = tid >> 5;
    const int lane = tid & 31;
    const int start = nb * BS;
    const size_t rowBase = (size_t)b * T * C + (size_t)h * D;

    const float* qp = q + rowBase;
    const float* kp = k + rowBase;
    const float* vp = v + rowBase;

    // --- cp.async loads: group 0 = Q + K (swizzled panels), group 1 = V ---
    {
        // Q: 64 rows x 16 granules
        #pragma unroll
        for (int i = 0; i < 4; i++) {
            const int idx = tid + i * 256;
            const int r = idx >> 4, g = idx & 15;
            CP_ASYNC16(sb + (g >> 3) * 8192 + r * 128 + (((g & 7) * 16) ^ ((r & 7) * 16)),
                       qp + (size_t)(start + r) * C + g * 4);
        }
        // K: 192 rows x 16 granules (rows clamped; masked later)
        #pragma unroll
        for (int i = 0; i < 12; i++) {
            const int idx = tid + i * 256;
            const int r = idx >> 4, g = idx & 15;
            int p = start - LW / 2 + r;
            p = p < 0 ? 0 : (p >= T ? T - 1 : p);
            CP_ASYNC16(sb + AOFF_K + (g >> 3) * 24576 + r * 128 + (((g & 7) * 16) ^ ((r & 7) * 16)),
                       kp + (size_t)p * C + g * 4);
        }
        CP_COMMIT();
        // V: 192 rows x 16 granules, plain rows of 288B
        #pragma unroll
        for (int i = 0; i < 12; i++) {
            const int idx = tid + i * 256;
            const int r = idx >> 4, g = idx & 15;
            int p = start - LW / 2 + r;
            p = p < 0 ? 0 : (p >= T ? T - 1 : p);
            CP_ASYNC16(sb + AOFF_V + r * 288 + g * 16,
                       vp + (size_t)p * C + g * 4);
        }
        CP_COMMIT();
    }

    const int r8 = lane & 7;
    const int qa = lane >> 3;
    const uint32_t xorp = (uint32_t)r8 * 16;

    // --- QK^T on tensor cores ---
    const int wmq = (wid & 3) * 16;          // q-rows
    const int wnq = (wid >> 2) * 96;         // k-cols
    const uint32_t aQ_rb = (wmq + (qa & 1) * 8 + r8) * 128;
    const uint32_t aQ_ks = (uint32_t)(qa >> 1) * 16;
    const uint32_t bK_rb = (wnq + (qa >> 1) * 8 + r8) * 128;
    const uint32_t bK_ks = (uint32_t)(qa & 1) * 16;

    float accS[12][4];
    #pragma unroll
    for (int i = 0; i < 12; i++)
        #pragma unroll
        for (int l = 0; l < 4; l++) accS[i][l] = 0.f;

    CP_WAIT(1);
    __syncthreads();

    #pragma unroll
    for (int pan = 0; pan < 2; pan++) {
        #pragma unroll
        for (int ks = 0; ks < 4; ks++) {
            const uint32_t akoff = ((uint32_t)ks * 32 + aQ_ks) ^ xorp;
            const uint32_t bkoff = ((uint32_t)ks * 32 + bK_ks) ^ xorp;
            uint32_t af[4], bf[6][4];
            LDSM_X4(af, sb + pan * 8192 + aQ_rb + akoff);
            #pragma unroll
            for (int p = 0; p < 6; p++)
                LDSM_X4(bf[p], sb + AOFF_K + pan * 24576 + bK_rb + p * (16 * 128) + bkoff);
            #pragma unroll
            for (int l = 0; l < 4; l++) af[l] = to_tf32(af[l]);
            #pragma unroll
            for (int p = 0; p < 6; p++)
                #pragma unroll
                for (int l = 0; l < 4; l++) bf[p][l] = to_tf32(bf[p][l]);
            #pragma unroll
            for (int p = 0; p < 6; p++) {
                MMA_TF32(accS[2 * p + 0], af, bf[p][0], bf[p][1]);
                MMA_TF32(accS[2 * p + 1], af, bf[p][2], bf[p][3]);
            }
        }
    }
    __syncthreads();   // all Q/K panel reads done -> safe to overlay Ssm

    // Scatter score fragments to Ssm
    {
        const int r0 = wmq + (lane >> 2);
        const int c0 = wnq + 2 * (lane & 3);
        #pragma unroll
        for (int nt = 0; nt < 12; nt++) {
            const int c = c0 + nt * 8;
            Ssm[r0 * SSTR + c]           = accS[nt][0];
            Ssm[r0 * SSTR + c + 1]       = accS[nt][1];
            Ssm[(r0 + 8) * SSTR + c]     = accS[nt][2];
            Ssm[(r0 + 8) * SSTR + c + 1] = accS[nt][3];
        }
    }
    CP_WAIT(0);        // V resident before PV
    __syncthreads();

    // Masked softmax; write P directly into swizzled panels
    {
        for (int r = wid; r < BS; r += 8) {
            float e[6];
            float mx = -INFINITY;
            #pragma unroll
            for (int t2 = 0; t2 < 6; t2++) {
                const int kj = lane + 32 * t2;
                const int p  = start - LW / 2 + kj;
                const float s = (p >= 0 && p < T) ? Ssm[r * SSTR + kj] : -INFINITY;
                e[t2] = s;
                mx = fmaxf(mx, s);
            }
            #pragma unroll
            for (int off = 16; off > 0; off >>= 1)
                mx = fmaxf(mx, __shfl_xor_sync(0xffffffffu, mx, off));
            float sum = 0.f;
            #pragma unroll
            for (int t2 = 0; t2 < 6; t2++) {
                const float ev = (e[t2] == -INFINITY) ? 0.f : __expf(e[t2] - mx);
                e[t2] = ev;
                sum += ev;
            }
            #pragma unroll
            for (int off = 16; off > 0; off >>= 1)
                sum += __shfl_xor_sync(0xffffffffu, sum, off);
            const float inv = 1.f / sum;
            const int gsw = (((lane >> 2) * 4) ^ ((r & 7) * 4)) + (lane & 3);
            #pragma unroll
            for (int t2 = 0; t2 < 6; t2++)
                Ppan[t2 * 2048 + r * 32 + gsw] = e[t2] * inv;
        }
    }
    __syncthreads();

    // --- P @ V on tensor cores (V B-fragments via direct LDS) ---
    const int wmp = (wid & 3) * 16;          // q-rows
    const int wnp = (wid >> 2) * 32;         // d-cols
    const uint32_t aP_rb = (wmp + (qa & 1) * 8 + r8) * 128;
    const uint32_t aP_ks = (uint32_t)(qa >> 1) * 16;

    float accO[4][4];
    #pragma unroll
    for (int i = 0; i < 4; i++)
        #pragma unroll
        for (int l = 0; l < 4; l++) accO[i][l] = 0.f;

    #pragma unroll
    for (int pan = 0; pan < 6; pan++) {
        #pragma unroll
        for (int ks = 0; ks < 4; ks++) {
            uint32_t af[4];
            LDSM_X4(af, sb + AOFF_P + pan * 8192 + aP_rb + (((uint32_t)ks * 32 + aP_ks) ^ xorp));
            #pragma unroll
            for (int l = 0; l < 4; l++) af[l] = to_tf32(af[l]);
            const int k0 = pan * 32 + ks * 8 + (lane & 3);
            #pragma unroll
            for (int nt = 0; nt < 4; nt++) {
                const int col = wnp + nt * 8 + (lane >> 2);
                const uint32_t b0 = f_to_tf32(Vsm[k0 * VSTRIDE_F + col]);
                const uint32_t b1 = f_to_tf32(Vsm[(k0 + 4) * VSTRIDE_F + col]);
                MMA_TF32(accO[nt], af, b0, b1);
            }
        }
    }

    // Write O
    {
        const int r0 = wmp + (lane >> 2);
        const int c0 = wnp + 2 * (lane & 3);
        #pragma unroll
        for (int nt = 0; nt < 4; nt++) {
            const int c = c0 + nt * 8;
            float2 lo, hi;
            lo.x = accO[nt][0]; lo.y = accO[nt][1];
            hi.x = accO[nt][2]; hi.y = accO[nt][3];
            *(float2*)(o + rowBase + (size_t)(start + r0) * C + c)     = lo;
            *(float2*)(o + rowBase + (size_t)(start + r0 + 8) * C + c) = hi;
        }
    }
}

// ---------------------------------------------------------------------------
extern "C" void kernel_launch(void* const* d_in, const int* in_sizes, int n_in,
                              void* d_out, int out_size)
{
    const float* query = (const float*)d_in[0];
    const float* key   = (const float*)d_in[1];
    const float* value = (const float*)d_in[2];
    const float* Wq    = (const float*)d_in[3];
    const float* bq    = (const float*)d_in[4];
    const float* Wk    = (const float*)d_in[5];
    const float* bk    = (const float*)d_in[6];
    const float* Wv    = (const float*)d_in[7];
    const float* bv    = (const float*)d_in[8];
    const float* Wo    = (const float*)d_in[9];
    const float* bo    = (const float*)d_in[10];
    float* out = (float*)d_out;

    float *gq, *gk, *gv, *ga;
    cudaGetSymbolAddress((void**)&gq, g_q);
    cudaGetSymbolAddress((void**)&gk, g_k);
    cudaGetSymbolAddress((void**)&gv, g_v);
    cudaGetSymbolAddress((void**)&ga, g_a);

    cudaFuncSetAttribute(gemm_mma,
                         cudaFuncAttributeMaxDynamicSharedMemorySize, SM_GEMM);
    cudaFuncSetAttribute(attn_kernel,
                         cudaFuncAttributeMaxDynamicSharedMemorySize, SMEM_ATTN);

    const dim3 gg(C / GBN, M / GBM);   // (4, 128)
    const float scale = 0.125f;        // 64^-0.5

    gemm_mma<<<gg, 256, SM_GEMM>>>(query, Wq, bq, gq, scale);
    gemm_mma<<<gg, 256, SM_GEMM>>>(key,   Wk, bk, gk, 1.0f);
    gemm_mma<<<gg, 256, SM_GEMM>>>(value, Wv, bv, gv, 1.0f);

    attn_kernel<<<dim3(NB, H, B), 256, SMEM_ATTN>>>(gq, gk, gv, ga);

    gemm_mma<<<gg, 256, SM_GEMM>>>(ga, Wo, bo, out, 1.0f);
}

// round 5
// speedup vs baseline: 3.8268x; 1.0869x over previous
#include <cuda_runtime.h>
#include <cuda_bf16.h>
#include <math.h>
#include <cstdint>

// ---------------------------------------------------------------------------
// Problem constants
// ---------------------------------------------------------------------------
constexpr int B  = 2;
constexpr int T  = 8192;
constexpr int C  = 1024;
constexpr int H  = 16;
constexpr int BS = 64;
constexpr int LW = 128;
constexpr int D  = 64;
constexpr int WN = BS + LW;     // 192
constexpr int NB = T / BS;      // 128
constexpr int M  = B * T;       // 16384

// ---------------------------------------------------------------------------
// GEMM config: mma.sync m16n8k8 tf32, CTA tile 128x128x32, 8 warps (32x64),
// 3-stage cp.async pipeline, 2 CTAs/SM.
// ---------------------------------------------------------------------------
constexpr int GBM = 128;
constexpr int GBN = 128;
constexpr int GBK = 32;
constexpr int NKT = C / GBK;                  // 32
constexpr int AST = GBM * GBK * 4;            // 16384
constexpr int BST = GBN * GBK * 4;            // 16384
constexpr int SM_B_OFF = 3 * AST;             // 49152
constexpr int SM_BIAS  = 3 * AST + 3 * BST;   // 98304
constexpr int SM_GEMM  = SM_BIAS + GBN * 4;   // 98816  (x2 CTAs = 197632)

// ---------------------------------------------------------------------------
// Attention smem layout (bytes) — unchanged from R4
// ---------------------------------------------------------------------------
constexpr int AOFF_K = 16384;
constexpr int AOFF_V = 65536;
constexpr int AOFF_P = 120832;
constexpr int SMEM_ATTN = AOFF_P + 6 * 64 * 128;   // 169984
constexpr int SSTR = 196;
constexpr int VSTRIDE_F = 72;                       // floats per V row (288B)

// ---------------------------------------------------------------------------
// Scratch
// ---------------------------------------------------------------------------
__device__ __align__(16) float g_q[(size_t)M * C];
__device__ __align__(16) float g_k[(size_t)M * C];
__device__ __align__(16) float g_v[(size_t)M * C];
__device__ __align__(16) float g_a[(size_t)M * C];

// ---------------------------------------------------------------------------
// PTX helpers (base sm_103-safe)
// ---------------------------------------------------------------------------
__device__ __forceinline__ uint32_t smem_u32(const void* p) {
    uint32_t a;
    asm("{ .reg .u64 t; cvta.to.shared.u64 t, %1; cvt.u32.u64 %0, t; }" : "=r"(a) : "l"(p));
    return a;
}

#define CP_ASYNC16(dst, src) \
    asm volatile("cp.async.cg.shared.global [%0], [%1], 16;" :: "r"(dst), "l"(src) : "memory")
#define CP_COMMIT() asm volatile("cp.async.commit_group;" ::: "memory")
#define CP_WAIT(n)  asm volatile("cp.async.wait_group %0;" :: "n"(n) : "memory")

#define LDSM_X4(r, addr) \
    asm volatile("ldmatrix.sync.aligned.m8n8.x4.shared.b16 {%0,%1,%2,%3}, [%4];" \
        : "=r"((r)[0]), "=r"((r)[1]), "=r"((r)[2]), "=r"((r)[3]) : "r"(addr))

#define MMA_TF32(d, a, b0, b1) \
    asm volatile("mma.sync.aligned.m16n8k8.row.col.f32.tf32.tf32.f32 " \
        "{%0,%1,%2,%3}, {%4,%5,%6,%7}, {%8,%9}, {%0,%1,%2,%3};" \
        : "+f"((d)[0]), "+f"((d)[1]), "+f"((d)[2]), "+f"((d)[3]) \
        : "r"((a)[0]), "r"((a)[1]), "r"((a)[2]), "r"((a)[3]), "r"(b0), "r"(b1))

__device__ __forceinline__ uint32_t to_tf32(uint32_t x) {
    uint32_t y;
    asm("cvt.rna.tf32.f32 %0, %1;" : "=r"(y) : "f"(__uint_as_float(x)));
    return y;
}
__device__ __forceinline__ uint32_t f_to_tf32(float x) {
    uint32_t y;
    asm("cvt.rna.tf32.f32 %0, %1;" : "=r"(y) : "f"(x));
    return y;
}

// ---------------------------------------------------------------------------
// GEMM: Y[m,n] = alpha * (sum_k A[m,k] * Wt[n,k] + bias[n])
// 128x128 CTA tile, warp tile 32x64 (4x2 warps), 2 CTAs/SM.
// ---------------------------------------------------------------------------
__global__ __launch_bounds__(256, 2)
void gemm_mma(const float* __restrict__ A, const float* __restrict__ Wt,
              const float* __restrict__ bias, float* __restrict__ Y, float alpha)
{
    extern __shared__ char smem[];
    const uint32_t sA = smem_u32(smem);
    const uint32_t sB = sA + SM_B_OFF;
    float* bsm = (float*)(smem + SM_BIAS);

    const int tid  = threadIdx.x;
    const int wid  = tid >> 5;
    const int lane = tid & 31;
    const int bm   = blockIdx.y * GBM;
    const int n0   = blockIdx.x * GBN;

    if (tid < GBN / 4)
        *(float4*)(bsm + tid * 4) = *(const float4*)(bias + n0 + tid * 4);

    auto loadA = [&](int slot, int kt) {
        const float* src = A + (size_t)bm * C + kt * GBK;
        const uint32_t base = sA + slot * AST;
        #pragma unroll
        for (int c = 0; c < 4; c++) {
            const int ci = tid + c * 256;
            const int r = ci >> 3, c16 = ci & 7;
            CP_ASYNC16(base + r * 128 + ((c16 * 16) ^ ((r & 7) * 16)),
                       src + (size_t)r * C + c16 * 4);
        }
    };
    auto loadB = [&](int slot, int kt) {
        const float* src = Wt + (size_t)n0 * C + kt * GBK;
        const uint32_t base = sB + slot * BST;
        #pragma unroll
        for (int c = 0; c < 4; c++) {
            const int ci = tid + c * 256;
            const int r = ci >> 3, c16 = ci & 7;
            CP_ASYNC16(base + r * 128 + ((c16 * 16) ^ ((r & 7) * 16)),
                       src + (size_t)r * C + c16 * 4);
        }
    };

    loadA(0, 0); loadB(0, 0); CP_COMMIT();
    loadA(1, 1); loadB(1, 1); CP_COMMIT();

    float acc[2][8][4];
    #pragma unroll
    for (int i = 0; i < 2; i++)
        #pragma unroll
        for (int j = 0; j < 8; j++)
            #pragma unroll
            for (int l = 0; l < 4; l++) acc[i][j][l] = 0.f;

    const int r8 = lane & 7;
    const int qa = lane >> 3;
    const int wm = (wid & 3) * 32;     // warp m offset
    const int wn = (wid >> 2) * 64;    // warp n offset
    const uint32_t a_rb   = (wm + (qa & 1) * 8 + r8) * 128;
    const uint32_t a_ksel = (uint32_t)(qa >> 1) * 16;
    const uint32_t b_rb   = (wn + (qa >> 1) * 8 + r8) * 128;
    const uint32_t b_ksel = (uint32_t)(qa & 1) * 16;
    const uint32_t xorp   = (uint32_t)r8 * 16;

    for (int kt = 0; kt < NKT; kt++) {
        if (kt < NKT - 2) { CP_WAIT(1); } else { CP_WAIT(0); }
        __syncthreads();
        if (kt + 2 < NKT) {
            const int s2 = (kt + 2) % 3;
            loadA(s2, kt + 2); loadB(s2, kt + 2); CP_COMMIT();
        }
        const int slot = kt % 3;
        const uint32_t aBase = sA + slot * AST + a_rb;
        const uint32_t bBase = sB + slot * BST + b_rb;

        #pragma unroll
        for (int ks = 0; ks < 4; ks++) {
            const uint32_t akoff = ((uint32_t)ks * 32 + a_ksel) ^ xorp;
            const uint32_t bkoff = ((uint32_t)ks * 32 + b_ksel) ^ xorp;
            uint32_t af[2][4], bf[4][4];
            #pragma unroll
            for (int mt = 0; mt < 2; mt++)
                LDSM_X4(af[mt], aBase + mt * (16 * 128) + akoff);
            #pragma unroll
            for (int p = 0; p < 4; p++)
                LDSM_X4(bf[p], bBase + p * (16 * 128) + bkoff);
            #pragma unroll
            for (int mt = 0; mt < 2; mt++)
                #pragma unroll
                for (int l = 0; l < 4; l++) af[mt][l] = to_tf32(af[mt][l]);
            #pragma unroll
            for (int p = 0; p < 4; p++)
                #pragma unroll
                for (int l = 0; l < 4; l++) bf[p][l] = to_tf32(bf[p][l]);
            #pragma unroll
            for (int mt = 0; mt < 2; mt++)
                #pragma unroll
                for (int p = 0; p < 4; p++) {
                    MMA_TF32(acc[mt][2 * p + 0], af[mt], bf[p][0], bf[p][1]);
                    MMA_TF32(acc[mt][2 * p + 1], af[mt], bf[p][2], bf[p][3]);
                }
        }
    }
    __syncthreads();

    const int erow  = bm + wm + (lane >> 2);
    const int ecol0 = wn + 2 * (lane & 3);
    #pragma unroll
    for (int mt = 0; mt < 2; mt++) {
        #pragma unroll
        for (int nt = 0; nt < 8; nt++) {
            const int col = ecol0 + nt * 8;
            const float b0 = bsm[col], b1 = bsm[col + 1];
            float2 lo, hi;
            lo.x = alpha * (acc[mt][nt][0] + b0);
            lo.y = alpha * (acc[mt][nt][1] + b1);
            hi.x = alpha * (acc[mt][nt][2] + b0);
            hi.y = alpha * (acc[mt][nt][3] + b1);
            *(float2*)(Y + (size_t)(erow + mt * 16)     * C + n0 + col) = lo;
            *(float2*)(Y + (size_t)(erow + mt * 16 + 8) * C + n0 + col) = hi;
        }
    }
}

// ---------------------------------------------------------------------------
// Tensor-core block-local attention (unchanged from R4).
// ---------------------------------------------------------------------------
__global__ __launch_bounds__(256, 1)
void attn_kernel(const float* __restrict__ q, const float* __restrict__ k,
                 const float* __restrict__ v, float* __restrict__ o)
{
    extern __shared__ char smem[];
    const uint32_t sb = smem_u32(smem);
    float* Ssm  = (float*)smem;                 // overlays Qpan+Kpan
    float* Vsm  = (float*)(smem + AOFF_V);
    float* Ppan = (float*)(smem + AOFF_P);

    const int nb  = blockIdx.x;
    const int h   = blockIdx.y;
    const int b   = blockIdx.z;
    const int tid = threadIdx.x;
    const int wid  = tid >> 5;
    const int lane = tid & 31;
    const int start = nb * BS;
    const size_t rowBase = (size_t)b * T * C + (size_t)h * D;

    const float* qp = q + rowBase;
    const float* kp = k + rowBase;
    const float* vp = v + rowBase;

    {
        #pragma unroll
        for (int i = 0; i < 4; i++) {
            const int idx = tid + i * 256;
            const int r = idx >> 4, g = idx & 15;
            CP_ASYNC16(sb + (g >> 3) * 8192 + r * 128 + (((g & 7) * 16) ^ ((r & 7) * 16)),
                       qp + (size_t)(start + r) * C + g * 4);
        }
        #pragma unroll
        for (int i = 0; i < 12; i++) {
            const int idx = tid + i * 256;
            const int r = idx >> 4, g = idx & 15;
            int p = start - LW / 2 + r;
            p = p < 0 ? 0 : (p >= T ? T - 1 : p);
            CP_ASYNC16(sb + AOFF_K + (g >> 3) * 24576 + r * 128 + (((g & 7) * 16) ^ ((r & 7) * 16)),
                       kp + (size_t)p * C + g * 4);
        }
        CP_COMMIT();
        #pragma unroll
        for (int i = 0; i < 12; i++) {
            const int idx = tid + i * 256;
            const int r = idx >> 4, g = idx & 15;
            int p = start - LW / 2 + r;
            p = p < 0 ? 0 : (p >= T ? T - 1 : p);
            CP_ASYNC16(sb + AOFF_V + r * 288 + g * 16,
                       vp + (size_t)p * C + g * 4);
        }
        CP_COMMIT();
    }

    const int r8 = lane & 7;
    const int qa = lane >> 3;
    const uint32_t xorp = (uint32_t)r8 * 16;

    const int wmq = (wid & 3) * 16;
    const int wnq = (wid >> 2) * 96;
    const uint32_t aQ_rb = (wmq + (qa & 1) * 8 + r8) * 128;
    const uint32_t aQ_ks = (uint32_t)(qa >> 1) * 16;
    const uint32_t bK_rb = (wnq + (qa >> 1) * 8 + r8) * 128;
    const uint32_t bK_ks = (uint32_t)(qa & 1) * 16;

    float accS[12][4];
    #pragma unroll
    for (int i = 0; i < 12; i++)
        #pragma unroll
        for (int l = 0; l < 4; l++) accS[i][l] = 0.f;

    CP_WAIT(1);
    __syncthreads();

    #pragma unroll
    for (int pan = 0; pan < 2; pan++) {
        #pragma unroll
        for (int ks = 0; ks < 4; ks++) {
            const uint32_t akoff = ((uint32_t)ks * 32 + aQ_ks) ^ xorp;
            const uint32_t bkoff = ((uint32_t)ks * 32 + bK_ks) ^ xorp;
            uint32_t af[4], bf[6][4];
            LDSM_X4(af, sb + pan * 8192 + aQ_rb + akoff);
            #pragma unroll
            for (int p = 0; p < 6; p++)
                LDSM_X4(bf[p], sb + AOFF_K + pan * 24576 + bK_rb + p * (16 * 128) + bkoff);
            #pragma unroll
            for (int l = 0; l < 4; l++) af[l] = to_tf32(af[l]);
            #pragma unroll
            for (int p = 0; p < 6; p++)
                #pragma unroll
                for (int l = 0; l < 4; l++) bf[p][l] = to_tf32(bf[p][l]);
            #pragma unroll
            for (int p = 0; p < 6; p++) {
                MMA_TF32(accS[2 * p + 0], af, bf[p][0], bf[p][1]);
                MMA_TF32(accS[2 * p + 1], af, bf[p][2], bf[p][3]);
            }
        }
    }
    __syncthreads();

    {
        const int r0 = wmq + (lane >> 2);
        const int c0 = wnq + 2 * (lane & 3);
        #pragma unroll
        for (int nt = 0; nt < 12; nt++) {
            const int c = c0 + nt * 8;
            Ssm[r0 * SSTR + c]           = accS[nt][0];
            Ssm[r0 * SSTR + c + 1]       = accS[nt][1];
            Ssm[(r0 + 8) * SSTR + c]     = accS[nt][2];
            Ssm[(r0 + 8) * SSTR + c + 1] = accS[nt][3];
        }
    }
    CP_WAIT(0);
    __syncthreads();

    {
        for (int r = wid; r < BS; r += 8) {
            float e[6];
            float mx = -INFINITY;
            #pragma unroll
            for (int t2 = 0; t2 < 6; t2++) {
                const int kj = lane + 32 * t2;
                const int p  = start - LW / 2 + kj;
                const float s = (p >= 0 && p < T) ? Ssm[r * SSTR + kj] : -INFINITY;
                e[t2] = s;
                mx = fmaxf(mx, s);
            }
            #pragma unroll
            for (int off = 16; off > 0; off >>= 1)
                mx = fmaxf(mx, __shfl_xor_sync(0xffffffffu, mx, off));
            float sum = 0.f;
            #pragma unroll
            for (int t2 = 0; t2 < 6; t2++) {
                const float ev = (e[t2] == -INFINITY) ? 0.f : __expf(e[t2] - mx);
                e[t2] = ev;
                sum += ev;
            }
            #pragma unroll
            for (int off = 16; off > 0; off >>= 1)
                sum += __shfl_xor_sync(0xffffffffu, sum, off);
            const float inv = 1.f / sum;
            const int gsw = (((lane >> 2) * 4) ^ ((r & 7) * 4)) + (lane & 3);
            #pragma unroll
            for (int t2 = 0; t2 < 6; t2++)
                Ppan[t2 * 2048 + r * 32 + gsw] = e[t2] * inv;
        }
    }
    __syncthreads();

    const int wmp = (wid & 3) * 16;
    const int wnp = (wid >> 2) * 32;
    const uint32_t aP_rb = (wmp + (qa & 1) * 8 + r8) * 128;
    const uint32_t aP_ks = (uint32_t)(qa >> 1) * 16;

    float accO[4][4];
    #pragma unroll
    for (int i = 0; i < 4; i++)
        #pragma unroll
        for (int l = 0; l < 4; l++) accO[i][l] = 0.f;

    #pragma unroll
    for (int pan = 0; pan < 6; pan++) {
        #pragma unroll
        for (int ks = 0; ks < 4; ks++) {
            uint32_t af[4];
            LDSM_X4(af, sb + AOFF_P + pan * 8192 + aP_rb + (((uint32_t)ks * 32 + aP_ks) ^ xorp));
            #pragma unroll
            for (int l = 0; l < 4; l++) af[l] = to_tf32(af[l]);
            const int k0 = pan * 32 + ks * 8 + (lane & 3);
            #pragma unroll
            for (int nt = 0; nt < 4; nt++) {
                const int col = wnp + nt * 8 + (lane >> 2);
                const uint32_t b0 = f_to_tf32(Vsm[k0 * VSTRIDE_F + col]);
                const uint32_t b1 = f_to_tf32(Vsm[(k0 + 4) * VSTRIDE_F + col]);
                MMA_TF32(accO[nt], af, b0, b1);
            }
        }
    }

    {
        const int r0 = wmp + (lane >> 2);
        const int c0 = wnp + 2 * (lane & 3);
        #pragma unroll
        for (int nt = 0; nt < 4; nt++) {
            const int c = c0 + nt * 8;
            float2 lo, hi;
            lo.x = accO[nt][0]; lo.y = accO[nt][1];
            hi.x = accO[nt][2]; hi.y = accO[nt][3];
            *(float2*)(o + rowBase + (size_t)(start + r0) * C + c)     = lo;
            *(float2*)(o + rowBase + (size_t)(start + r0 + 8) * C + c) = hi;
        }
    }
}

// ---------------------------------------------------------------------------
extern "C" void kernel_launch(void* const* d_in, const int* in_sizes, int n_in,
                              void* d_out, int out_size)
{
    const float* query = (const float*)d_in[0];
    const float* key   = (const float*)d_in[1];
    const float* value = (const float*)d_in[2];
    const float* Wq    = (const float*)d_in[3];
    const float* bq    = (const float*)d_in[4];
    const float* Wk    = (const float*)d_in[5];
    const float* bk    = (const float*)d_in[6];
    const float* Wv    = (const float*)d_in[7];
    const float* bv    = (const float*)d_in[8];
    const float* Wo    = (const float*)d_in[9];
    const float* bo    = (const float*)d_in[10];
    float* out = (float*)d_out;

    float *gq, *gk, *gv, *ga;
    cudaGetSymbolAddress((void**)&gq, g_q);
    cudaGetSymbolAddress((void**)&gk, g_k);
    cudaGetSymbolAddress((void**)&gv, g_v);
    cudaGetSymbolAddress((void**)&ga, g_a);

    cudaFuncSetAttribute(gemm_mma,
                         cudaFuncAttributeMaxDynamicSharedMemorySize, SM_GEMM);
    cudaFuncSetAttribute(attn_kernel,
                         cudaFuncAttributeMaxDynamicSharedMemorySize, SMEM_ATTN);

    const dim3 gg(C / GBN, M / GBM);   // (8, 128)
    const float scale = 0.125f;        // 64^-0.5

    gemm_mma<<<gg, 256, SM_GEMM>>>(query, Wq, bq, gq, scale);
    gemm_mma<<<gg, 256, SM_GEMM>>>(key,   Wk, bk, gk, 1.0f);
    gemm_mma<<<gg, 256, SM_GEMM>>>(value, Wv, bv, gv, 1.0f);

    attn_kernel<<<dim3(NB, H, B), 256, SMEM_ATTN>>>(gq, gk, gv, ga);

    gemm_mma<<<gg, 256, SM_GEMM>>>(ga, Wo, bo, out, 1.0f);
}

// round 6
// speedup vs baseline: 4.3053x; 1.1250x over previous
#include <cuda_runtime.h>
#include <cuda_bf16.h>
#include <math.h>
#include <cstdint>

// ---------------------------------------------------------------------------
// Problem constants
// ---------------------------------------------------------------------------
constexpr int B  = 2;
constexpr int T  = 8192;
constexpr int C  = 1024;
constexpr int H  = 16;
constexpr int BS = 64;
constexpr int LW = 128;
constexpr int D  = 64;
constexpr int WN = BS + LW;     // 192
constexpr int NB = T / BS;      // 128
constexpr int M  = B * T;       // 16384

// ---------------------------------------------------------------------------
// GEMM config: mma.sync m16n8k8 tf32, CTA tile 128x128x32, 8 warps (32x64),
// 3-stage cp.async pipeline, 2 CTAs/SM.
// ---------------------------------------------------------------------------
constexpr int GBM = 128;
constexpr int GBN = 128;
constexpr int GBK = 32;
constexpr int NKT = C / GBK;                  // 32
constexpr int AST = GBM * GBK * 4;            // 16384
constexpr int BST = GBN * GBK * 4;            // 16384
constexpr int SM_B_OFF = 3 * AST;             // 49152
constexpr int SM_BIAS  = 3 * AST + 3 * BST;   // 98304
constexpr int SM_GEMM  = SM_BIAS + GBN * 4;   // 98816  (x2 CTAs = 197632)

// ---------------------------------------------------------------------------
// Attention smem layout (bytes)
// ---------------------------------------------------------------------------
constexpr int AOFF_K = 16384;
constexpr int AOFF_V = 65536;
constexpr int AOFF_P = 120832;
constexpr int SMEM_ATTN = AOFF_P + 6 * 64 * 128;   // 169984
constexpr int SSTR = 196;
constexpr int VSTRIDE_F = 72;                       // floats per V row (288B)
constexpr int ATHR = 512;                           // attention threads

// ---------------------------------------------------------------------------
// Scratch
// ---------------------------------------------------------------------------
__device__ __align__(16) float g_q[(size_t)M * C];
__device__ __align__(16) float g_k[(size_t)M * C];
__device__ __align__(16) float g_v[(size_t)M * C];
__device__ __align__(16) float g_a[(size_t)M * C];
__device__ __align__(16) float g_w4[4][(size_t)C * C];   // tf32-rounded weights

struct GemmArgs {
    const float* A[3];
    const float* W[3];
    const float* bias[3];
    float*       Y[3];
    float        alpha[3];
};

// ---------------------------------------------------------------------------
// PTX helpers (base sm_103-safe)
// ---------------------------------------------------------------------------
__device__ __forceinline__ uint32_t smem_u32(const void* p) {
    uint32_t a;
    asm("{ .reg .u64 t; cvta.to.shared.u64 t, %1; cvt.u32.u64 %0, t; }" : "=r"(a) : "l"(p));
    return a;
}

#define CP_ASYNC16(dst, src) \
    asm volatile("cp.async.cg.shared.global [%0], [%1], 16;" :: "r"(dst), "l"(src) : "memory")
#define CP_COMMIT() asm volatile("cp.async.commit_group;" ::: "memory")
#define CP_WAIT(n)  asm volatile("cp.async.wait_group %0;" :: "n"(n) : "memory")

#define LDSM_X4(r, addr) \
    asm volatile("ldmatrix.sync.aligned.m8n8.x4.shared.b16 {%0,%1,%2,%3}, [%4];" \
        : "=r"((r)[0]), "=r"((r)[1]), "=r"((r)[2]), "=r"((r)[3]) : "r"(addr))

#define MMA_TF32(d, a, b0, b1) \
    asm volatile("mma.sync.aligned.m16n8k8.row.col.f32.tf32.tf32.f32 " \
        "{%0,%1,%2,%3}, {%4,%5,%6,%7}, {%8,%9}, {%0,%1,%2,%3};" \
        : "+f"((d)[0]), "+f"((d)[1]), "+f"((d)[2]), "+f"((d)[3]) \
        : "r"((a)[0]), "r"((a)[1]), "r"((a)[2]), "r"((a)[3]), "r"(b0), "r"(b1))

__device__ __forceinline__ uint32_t to_tf32(uint32_t x) {
    uint32_t y;
    asm("cvt.rna.tf32.f32 %0, %1;" : "=r"(y) : "f"(__uint_as_float(x)));
    return y;
}
__device__ __forceinline__ uint32_t f_to_tf32(float x) {
    uint32_t y;
    asm("cvt.rna.tf32.f32 %0, %1;" : "=r"(y) : "f"(x));
    return y;
}

// ---------------------------------------------------------------------------
// Prepass: round the 4 weight matrices to tf32 (rna) once.
// ---------------------------------------------------------------------------
__global__ __launch_bounds__(256)
void round_weights(const float4* __restrict__ w0, const float4* __restrict__ w1,
                   const float4* __restrict__ w2, const float4* __restrict__ w3)
{
    constexpr int PER = C * C / 4;   // float4 per matrix = 262144
    const int i = blockIdx.x * 256 + threadIdx.x;
    const int which = i / PER;
    const int off   = i - which * PER;
    const float4* src = which == 0 ? w0 : which == 1 ? w1 : which == 2 ? w2 : w3;
    float4 v = src[off];
    float4 o;
    o.x = __uint_as_float(f_to_tf32(v.x));
    o.y = __uint_as_float(f_to_tf32(v.y));
    o.z = __uint_as_float(f_to_tf32(v.z));
    o.w = __uint_as_float(f_to_tf32(v.w));
    *(float4*)&g_w4[which][(size_t)off * 4] = o;
}

// ---------------------------------------------------------------------------
// GEMM: Y[m,n] = alpha * (sum_k A[m,k] * W[n,k] + bias[n])
// blockIdx.z selects the operand set (QKV merged launch / out launch).
// Weights are pre-rounded to tf32 (no B-side cvt).
// ---------------------------------------------------------------------------
__global__ __launch_bounds__(256, 2)
void gemm_mma(const GemmArgs args)
{
    extern __shared__ char smem[];
    const uint32_t sA = smem_u32(smem);
    const uint32_t sB = sA + SM_B_OFF;
    float* bsm = (float*)(smem + SM_BIAS);

    const int z = blockIdx.z;
    const float* A    = args.A[z];
    const float* Wt   = args.W[z];
    const float* bias = args.bias[z];
    float*       Y    = args.Y[z];
    const float alpha = args.alpha[z];

    const int tid  = threadIdx.x;
    const int wid  = tid >> 5;
    const int lane = tid & 31;
    const int bm   = blockIdx.y * GBM;
    const int n0   = blockIdx.x * GBN;

    if (tid < GBN / 4)
        *(float4*)(bsm + tid * 4) = *(const float4*)(bias + n0 + tid * 4);

    auto loadA = [&](int slot, int kt) {
        const float* src = A + (size_t)bm * C + kt * GBK;
        const uint32_t base = sA + slot * AST;
        #pragma unroll
        for (int c = 0; c < 4; c++) {
            const int ci = tid + c * 256;
            const int r = ci >> 3, c16 = ci & 7;
            CP_ASYNC16(base + r * 128 + ((c16 * 16) ^ ((r & 7) * 16)),
                       src + (size_t)r * C + c16 * 4);
        }
    };
    auto loadB = [&](int slot, int kt) {
        const float* src = Wt + (size_t)n0 * C + kt * GBK;
        const uint32_t base = sB + slot * BST;
        #pragma unroll
        for (int c = 0; c < 4; c++) {
            const int ci = tid + c * 256;
            const int r = ci >> 3, c16 = ci & 7;
            CP_ASYNC16(base + r * 128 + ((c16 * 16) ^ ((r & 7) * 16)),
                       src + (size_t)r * C + c16 * 4);
        }
    };

    loadA(0, 0); loadB(0, 0); CP_COMMIT();
    loadA(1, 1); loadB(1, 1); CP_COMMIT();

    float acc[2][8][4];
    #pragma unroll
    for (int i = 0; i < 2; i++)
        #pragma unroll
        for (int j = 0; j < 8; j++)
            #pragma unroll
            for (int l = 0; l < 4; l++) acc[i][j][l] = 0.f;

    const int r8 = lane & 7;
    const int qa = lane >> 3;
    const int wm = (wid & 3) * 32;     // warp m offset
    const int wn = (wid >> 2) * 64;    // warp n offset
    const uint32_t a_rb   = (wm + (qa & 1) * 8 + r8) * 128;
    const uint32_t a_ksel = (uint32_t)(qa >> 1) * 16;
    const uint32_t b_rb   = (wn + (qa >> 1) * 8 + r8) * 128;
    const uint32_t b_ksel = (uint32_t)(qa & 1) * 16;
    const uint32_t xorp   = (uint32_t)r8 * 16;

    for (int kt = 0; kt < NKT; kt++) {
        if (kt < NKT - 2) { CP_WAIT(1); } else { CP_WAIT(0); }
        __syncthreads();
        if (kt + 2 < NKT) {
            const int s2 = (kt + 2) % 3;
            loadA(s2, kt + 2); loadB(s2, kt + 2); CP_COMMIT();
        }
        const int slot = kt % 3;
        const uint32_t aBase = sA + slot * AST + a_rb;
        const uint32_t bBase = sB + slot * BST + b_rb;

        #pragma unroll
        for (int ks = 0; ks < 4; ks++) {
            const uint32_t akoff = ((uint32_t)ks * 32 + a_ksel) ^ xorp;
            const uint32_t bkoff = ((uint32_t)ks * 32 + b_ksel) ^ xorp;
            uint32_t af[2][4], bf[4][4];
            #pragma unroll
            for (int mt = 0; mt < 2; mt++)
                LDSM_X4(af[mt], aBase + mt * (16 * 128) + akoff);
            #pragma unroll
            for (int p = 0; p < 4; p++)
                LDSM_X4(bf[p], bBase + p * (16 * 128) + bkoff);
            #pragma unroll
            for (int mt = 0; mt < 2; mt++)
                #pragma unroll
                for (int l = 0; l < 4; l++) af[mt][l] = to_tf32(af[mt][l]);
            // weights pre-rounded: no bf cvt
            #pragma unroll
            for (int mt = 0; mt < 2; mt++)
                #pragma unroll
                for (int p = 0; p < 4; p++) {
                    MMA_TF32(acc[mt][2 * p + 0], af[mt], bf[p][0], bf[p][1]);
                    MMA_TF32(acc[mt][2 * p + 1], af[mt], bf[p][2], bf[p][3]);
                }
        }
    }
    __syncthreads();

    const int erow  = bm + wm + (lane >> 2);
    const int ecol0 = wn + 2 * (lane & 3);
    #pragma unroll
    for (int mt = 0; mt < 2; mt++) {
        #pragma unroll
        for (int nt = 0; nt < 8; nt++) {
            const int col = ecol0 + nt * 8;
            const float b0 = bsm[col], b1 = bsm[col + 1];
            float2 lo, hi;
            lo.x = alpha * (acc[mt][nt][0] + b0);
            lo.y = alpha * (acc[mt][nt][1] + b1);
            hi.x = alpha * (acc[mt][nt][2] + b0);
            hi.y = alpha * (acc[mt][nt][3] + b1);
            *(float2*)(Y + (size_t)(erow + mt * 16)     * C + n0 + col) = lo;
            *(float2*)(Y + (size_t)(erow + mt * 16 + 8) * C + n0 + col) = hi;
        }
    }
}

// ---------------------------------------------------------------------------
// Tensor-core block-local attention, 512 threads (16 warps), 1 CTA/(nb,h,b).
// QK: warp grid 4x4 over 64x192 (tile 16x48). PV: 4x4 over 64x64 (tile 16x16).
// ---------------------------------------------------------------------------
__global__ __launch_bounds__(ATHR, 1)
void attn_kernel(const float* __restrict__ q, const float* __restrict__ k,
                 const float* __restrict__ v, float* __restrict__ o)
{
    extern __shared__ char smem[];
    const uint32_t sb = smem_u32(smem);
    float* Ssm  = (float*)smem;                 // overlays Qpan+Kpan
    float* Vsm  = (float*)(smem + AOFF_V);
    float* Ppan = (float*)(smem + AOFF_P);

    const int nb  = blockIdx.x;
    const int h   = blockIdx.y;
    const int b   = blockIdx.z;
    const int tid = threadIdx.x;
    const int wid  = tid >> 5;
    const int lane = tid & 31;
    const int start = nb * BS;
    const size_t rowBase = (size_t)b * T * C + (size_t)h * D;

    const float* qp = q + rowBase;
    const float* kp = k + rowBase;
    const float* vp = v + rowBase;

    // --- cp.async loads: group 0 = Q + K (swizzled panels), group 1 = V ---
    {
        #pragma unroll
        for (int i = 0; i < 2; i++) {
            const int idx = tid + i * ATHR;
            const int r = idx >> 4, g = idx & 15;
            CP_ASYNC16(sb + (g >> 3) * 8192 + r * 128 + (((g & 7) * 16) ^ ((r & 7) * 16)),
                       qp + (size_t)(start + r) * C + g * 4);
        }
        #pragma unroll
        for (int i = 0; i < 6; i++) {
            const int idx = tid + i * ATHR;
            const int r = idx >> 4, g = idx & 15;
            int p = start - LW / 2 + r;
            p = p < 0 ? 0 : (p >= T ? T - 1 : p);
            CP_ASYNC16(sb + AOFF_K + (g >> 3) * 24576 + r * 128 + (((g & 7) * 16) ^ ((r & 7) * 16)),
                       kp + (size_t)p * C + g * 4);
        }
        CP_COMMIT();
        #pragma unroll
        for (int i = 0; i < 6; i++) {
            const int idx = tid + i * ATHR;
            const int r = idx >> 4, g = idx & 15;
            int p = start - LW / 2 + r;
            p = p < 0 ? 0 : (p >= T ? T - 1 : p);
            CP_ASYNC16(sb + AOFF_V + r * 288 + g * 16,
                       vp + (size_t)p * C + g * 4);
        }
        CP_COMMIT();
    }

    const int r8 = lane & 7;
    const int qa = lane >> 3;
    const uint32_t xorp = (uint32_t)r8 * 16;

    // --- QK^T: warp tile 16 q-rows x 48 k-cols ---
    const int wmq = (wid & 3) * 16;
    const int wnq = (wid >> 2) * 48;
    const uint32_t aQ_rb = (wmq + (qa & 1) * 8 + r8) * 128;
    const uint32_t aQ_ks = (uint32_t)(qa >> 1) * 16;
    const uint32_t bK_rb = (wnq + (qa >> 1) * 8 + r8) * 128;
    const uint32_t bK_ks = (uint32_t)(qa & 1) * 16;

    float accS[6][4];
    #pragma unroll
    for (int i = 0; i < 6; i++)
        #pragma unroll
        for (int l = 0; l < 4; l++) accS[i][l] = 0.f;

    CP_WAIT(1);
    __syncthreads();

    #pragma unroll
    for (int pan = 0; pan < 2; pan++) {
        #pragma unroll
        for (int ks = 0; ks < 4; ks++) {
            const uint32_t akoff = ((uint32_t)ks * 32 + aQ_ks) ^ xorp;
            const uint32_t bkoff = ((uint32_t)ks * 32 + bK_ks) ^ xorp;
            uint32_t af[4], bf[3][4];
            LDSM_X4(af, sb + pan * 8192 + aQ_rb + akoff);
            #pragma unroll
            for (int p = 0; p < 3; p++)
                LDSM_X4(bf[p], sb + AOFF_K + pan * 24576 + bK_rb + p * (16 * 128) + bkoff);
            #pragma unroll
            for (int l = 0; l < 4; l++) af[l] = to_tf32(af[l]);
            #pragma unroll
            for (int p = 0; p < 3; p++)
                #pragma unroll
                for (int l = 0; l < 4; l++) bf[p][l] = to_tf32(bf[p][l]);
            #pragma unroll
            for (int p = 0; p < 3; p++) {
                MMA_TF32(accS[2 * p + 0], af, bf[p][0], bf[p][1]);
                MMA_TF32(accS[2 * p + 1], af, bf[p][2], bf[p][3]);
            }
        }
    }
    __syncthreads();   // Q/K panel reads done -> safe to overlay Ssm

    // Scatter score fragments to Ssm
    {
        const int r0 = wmq + (lane >> 2);
        const int c0 = wnq + 2 * (lane & 3);
        #pragma unroll
        for (int nt = 0; nt < 6; nt++) {
            const int c = c0 + nt * 8;
            Ssm[r0 * SSTR + c]           = accS[nt][0];
            Ssm[r0 * SSTR + c + 1]       = accS[nt][1];
            Ssm[(r0 + 8) * SSTR + c]     = accS[nt][2];
            Ssm[(r0 + 8) * SSTR + c + 1] = accS[nt][3];
        }
    }
    CP_WAIT(0);        // V resident before PV
    __syncthreads();

    // Masked softmax; write P directly into swizzled panels (4 rows/warp)
    {
        #pragma unroll
        for (int r = wid; r < BS; r += 16) {
            float e[6];
            float mx = -INFINITY;
            #pragma unroll
            for (int t2 = 0; t2 < 6; t2++) {
                const int kj = lane + 32 * t2;
                const int p  = start - LW / 2 + kj;
                const float s = (p >= 0 && p < T) ? Ssm[r * SSTR + kj] : -INFINITY;
                e[t2] = s;
                mx = fmaxf(mx, s);
            }
            #pragma unroll
            for (int off = 16; off > 0; off >>= 1)
                mx = fmaxf(mx, __shfl_xor_sync(0xffffffffu, mx, off));
            float sum = 0.f;
            #pragma unroll
            for (int t2 = 0; t2 < 6; t2++) {
                const float ev = (e[t2] == -INFINITY) ? 0.f : __expf(e[t2] - mx);
                e[t2] = ev;
                sum += ev;
            }
            #pragma unroll
            for (int off = 16; off > 0; off >>= 1)
                sum += __shfl_xor_sync(0xffffffffu, sum, off);
            const float inv = 1.f / sum;
            const int gsw = (((lane >> 2) * 4) ^ ((r & 7) * 4)) + (lane & 3);
            #pragma unroll
            for (int t2 = 0; t2 < 6; t2++)
                Ppan[t2 * 2048 + r * 32 + gsw] = e[t2] * inv;
        }
    }
    __syncthreads();

    // --- P @ V: warp tile 16 q-rows x 16 d-cols ---
    const int wmp = (wid & 3) * 16;
    const int wnp = (wid >> 2) * 16;
    const uint32_t aP_rb = (wmp + (qa & 1) * 8 + r8) * 128;
    const uint32_t aP_ks = (uint32_t)(qa >> 1) * 16;

    float accO[2][4];
    #pragma unroll
    for (int i = 0; i < 2; i++)
        #pragma unroll
        for (int l = 0; l < 4; l++) accO[i][l] = 0.f;

    #pragma unroll
    for (int pan = 0; pan < 6; pan++) {
        #pragma unroll
        for (int ks = 0; ks < 4; ks++) {
            uint32_t af[4];
            LDSM_X4(af, sb + AOFF_P + pan * 8192 + aP_rb + (((uint32_t)ks * 32 + aP_ks) ^ xorp));
            #pragma unroll
            for (int l = 0; l < 4; l++) af[l] = to_tf32(af[l]);
            const int k0 = pan * 32 + ks * 8 + (lane & 3);
            #pragma unroll
            for (int nt = 0; nt < 2; nt++) {
                const int col = wnp + nt * 8 + (lane >> 2);
                const uint32_t b0 = f_to_tf32(Vsm[k0 * VSTRIDE_F + col]);
                const uint32_t b1 = f_to_tf32(Vsm[(k0 + 4) * VSTRIDE_F + col]);
                MMA_TF32(accO[nt], af, b0, b1);
            }
        }
    }

    // Write O
    {
        const int r0 = wmp + (lane >> 2);
        const int c0 = wnp + 2 * (lane & 3);
        #pragma unroll
        for (int nt = 0; nt < 2; nt++) {
            const int c = c0 + nt * 8;
            float2 lo, hi;
            lo.x = accO[nt][0]; lo.y = accO[nt][1];
            hi.x = accO[nt][2]; hi.y = accO[nt][3];
            *(float2*)(o + rowBase + (size_t)(start + r0) * C + c)     = lo;
            *(float2*)(o + rowBase + (size_t)(start + r0 + 8) * C + c) = hi;
        }
    }
}

// ---------------------------------------------------------------------------
extern "C" void kernel_launch(void* const* d_in, const int* in_sizes, int n_in,
                              void* d_out, int out_size)
{
    const float* query = (const float*)d_in[0];
    const float* key   = (const float*)d_in[1];
    const float* value = (const float*)d_in[2];
    const float* Wq    = (const float*)d_in[3];
    const float* bq    = (const float*)d_in[4];
    const float* Wk    = (const float*)d_in[5];
    const float* bk    = (const float*)d_in[6];
    const float* Wv    = (const float*)d_in[7];
    const float* bv    = (const float*)d_in[8];
    const float* Wo    = (const float*)d_in[9];
    const float* bo    = (const float*)d_in[10];
    float* out = (float*)d_out;

    float *gq, *gk, *gv, *ga, *gw;
    cudaGetSymbolAddress((void**)&gq, g_q);
    cudaGetSymbolAddress((void**)&gk, g_k);
    cudaGetSymbolAddress((void**)&gv, g_v);
    cudaGetSymbolAddress((void**)&ga, g_a);
    cudaGetSymbolAddress((void**)&gw, g_w4);
    const float* w0 = gw;
    const float* w1 = gw + (size_t)C * C;
    const float* w2 = gw + (size_t)2 * C * C;
    const float* w3 = gw + (size_t)3 * C * C;

    cudaFuncSetAttribute(gemm_mma,
                         cudaFuncAttributeMaxDynamicSharedMemorySize, SM_GEMM);
    cudaFuncSetAttribute(attn_kernel,
                         cudaFuncAttributeMaxDynamicSharedMemorySize, SMEM_ATTN);

    // Round all weights to tf32 once (4 * 1M floats)
    round_weights<<<(4 * C * C / 4) / 256, 256>>>(
        (const float4*)Wq, (const float4*)Wk, (const float4*)Wv, (const float4*)Wo);

    const float scale = 0.125f;   // 64^-0.5

    // Merged Q/K/V projection launch: grid.z selects operand set
    GemmArgs qkv;
    qkv.A[0] = query; qkv.A[1] = key; qkv.A[2] = value;
    qkv.W[0] = w0;    qkv.W[1] = w1;  qkv.W[2] = w2;
    qkv.bias[0] = bq; qkv.bias[1] = bk; qkv.bias[2] = bv;
    qkv.Y[0] = gq;    qkv.Y[1] = gk;  qkv.Y[2] = gv;
    qkv.alpha[0] = scale; qkv.alpha[1] = 1.0f; qkv.alpha[2] = 1.0f;
    gemm_mma<<<dim3(C / GBN, M / GBM, 3), 256, SM_GEMM>>>(qkv);

    attn_kernel<<<dim3(NB, H, B), ATHR, SMEM_ATTN>>>(gq, gk, gv, ga);

    GemmArgs og;
    og.A[0] = ga; og.A[1] = ga; og.A[2] = ga;
    og.W[0] = w3; og.W[1] = w3; og.W[2] = w3;
    og.bias[0] = bo; og.bias[1] = bo; og.bias[2] = bo;
    og.Y[0] = out; og.Y[1] = out; og.Y[2] = out;
    og.alpha[0] = 1.0f; og.alpha[1] = 1.0f; og.alpha[2] = 1.0f;
    gemm_mma<<<dim3(C / GBN, M / GBM, 1), 256, SM_GEMM>>>(og);
}

// round 7
// speedup vs baseline: 7.3749x; 1.7130x over previous
#include <cuda_runtime.h>
#include <cuda_fp16.h>
#include <math.h>
#include <cstdint>

// ---------------------------------------------------------------------------
// Problem constants
// ---------------------------------------------------------------------------
constexpr int B  = 2;
constexpr int T  = 8192;
constexpr int C  = 1024;
constexpr int H  = 16;
constexpr int BS = 64;
constexpr int LW = 128;
constexpr int D  = 64;
constexpr int WN = BS + LW;     // 192
constexpr int NB = T / BS;      // 128
constexpr int M  = B * T;       // 16384

// ---------------------------------------------------------------------------
// GEMM config: mma.sync m16n8k16 fp16, CTA tile 128x128x64, 8 warps (32x64),
// 3-stage cp.async pipeline, 2 CTAs/SM.
// ---------------------------------------------------------------------------
constexpr int GBM = 128;
constexpr int GBN = 128;
constexpr int GBK = 64;                       // 64 fp16 = 128B rows
constexpr int NKT = C / GBK;                  // 16
constexpr int AST = GBM * GBK * 2;            // 16384 B
constexpr int BST = GBN * GBK * 2;            // 16384 B
constexpr int SM_B_OFF = 3 * AST;             // 49152
constexpr int SM_BIAS  = 3 * AST + 3 * BST;   // 98304
constexpr int SM_GEMM  = SM_BIAS + GBN * 4;   // 98816

// ---------------------------------------------------------------------------
// Attention smem layout (bytes), all fp16 tiles, 128B rows
// ---------------------------------------------------------------------------
constexpr int SMQ   = 0;        // 64 x 128B = 8KB
constexpr int SMK   = 8192;     // 192 x 128B = 24KB
constexpr int SMV   = 32768;    // 192 x 128B = 24KB
constexpr int SMP   = 57344;    // 3 panels x 64 x 128B = 24KB
constexpr int SMRA  = 81920;    // 64 x 4 f32 (max reduce)
constexpr int SMRB  = 82944;    // 64 x 4 f32 (sum reduce)
constexpr int SMEM_ATTN = 83968;
constexpr int ATHR = 512;

// ---------------------------------------------------------------------------
// Scratch
// ---------------------------------------------------------------------------
__device__ __align__(16) __half g_x16[3][(size_t)M * C];   // fp16 inputs
__device__ __align__(16) __half g_w16[4][(size_t)C * C];   // fp16 weights
__device__ __align__(16) __half g_q[(size_t)M * C];
__device__ __align__(16) __half g_k[(size_t)M * C];
__device__ __align__(16) __half g_v[(size_t)M * C];
__device__ __align__(16) __half g_a[(size_t)M * C];

struct GemmArgs {
    const __half* A[3];
    const __half* W[3];
    const float*  bias[3];
    void*         Y[3];
    float         alpha[3];
};

// ---------------------------------------------------------------------------
// PTX helpers (base sm_103-safe)
// ---------------------------------------------------------------------------
__device__ __forceinline__ uint32_t smem_u32(const void* p) {
    uint32_t a;
    asm("{ .reg .u64 t; cvta.to.shared.u64 t, %1; cvt.u32.u64 %0, t; }" : "=r"(a) : "l"(p));
    return a;
}

#define CP_ASYNC16(dst, src) \
    asm volatile("cp.async.cg.shared.global [%0], [%1], 16;" :: "r"(dst), "l"(src) : "memory")
#define CP_COMMIT() asm volatile("cp.async.commit_group;" ::: "memory")
#define CP_WAIT(n)  asm volatile("cp.async.wait_group %0;" :: "n"(n) : "memory")

#define LDSM_X4(r, addr) \
    asm volatile("ldmatrix.sync.aligned.m8n8.x4.shared.b16 {%0,%1,%2,%3}, [%4];" \
        : "=r"((r)[0]), "=r"((r)[1]), "=r"((r)[2]), "=r"((r)[3]) : "r"(addr))

#define LDSM_X4_T(r, addr) \
    asm volatile("ldmatrix.sync.aligned.m8n8.x4.trans.shared.b16 {%0,%1,%2,%3}, [%4];" \
        : "=r"((r)[0]), "=r"((r)[1]), "=r"((r)[2]), "=r"((r)[3]) : "r"(addr))

#define MMA_F16(d, a, b0, b1) \
    asm volatile("mma.sync.aligned.m16n8k16.row.col.f32.f16.f16.f32 " \
        "{%0,%1,%2,%3}, {%4,%5,%6,%7}, {%8,%9}, {%0,%1,%2,%3};" \
        : "+f"((d)[0]), "+f"((d)[1]), "+f"((d)[2]), "+f"((d)[3]) \
        : "r"((a)[0]), "r"((a)[1]), "r"((a)[2]), "r"((a)[3]), "r"(b0), "r"(b1))

// ---------------------------------------------------------------------------
// Prepass: fp32 -> fp16 conversions
// ---------------------------------------------------------------------------
__global__ __launch_bounds__(256)
void conv_act(const float4* __restrict__ q, const float4* __restrict__ k,
              const float4* __restrict__ v)
{
    constexpr int PER4 = M * C / 4;
    const int i = blockIdx.x * 256 + threadIdx.x;
    const int which = i / PER4;
    const int off   = i - which * PER4;
    const float4* src = which == 0 ? q : which == 1 ? k : v;
    float4 x = src[off];
    __half2 h0 = __floats2half2_rn(x.x, x.y);
    __half2 h1 = __floats2half2_rn(x.z, x.w);
    __half2* dst = (__half2*)&g_x16[which][(size_t)off * 4];
    dst[0] = h0; dst[1] = h1;
}

__global__ __launch_bounds__(256)
void conv_weights(const float4* __restrict__ w0, const float4* __restrict__ w1,
                  const float4* __restrict__ w2, const float4* __restrict__ w3)
{
    constexpr int PER4 = C * C / 4;
    const int i = blockIdx.x * 256 + threadIdx.x;
    const int which = i / PER4;
    const int off   = i - which * PER4;
    const float4* src = which == 0 ? w0 : which == 1 ? w1 : which == 2 ? w2 : w3;
    float4 x = src[off];
    __half2 h0 = __floats2half2_rn(x.x, x.y);
    __half2 h1 = __floats2half2_rn(x.z, x.w);
    __half2* dst = (__half2*)&g_w16[which][(size_t)off * 4];
    dst[0] = h0; dst[1] = h1;
}

// ---------------------------------------------------------------------------
// fp16 GEMM: Y[m,n] = alpha * (sum_k A[m,k] * W[n,k] + bias[n])
// ---------------------------------------------------------------------------
template <bool HALF_OUT>
__global__ __launch_bounds__(256, 2)
void gemm_mma(const GemmArgs args)
{
    extern __shared__ char smem[];
    const uint32_t sA = smem_u32(smem);
    const uint32_t sB = sA + SM_B_OFF;
    float* bsm = (float*)(smem + SM_BIAS);

    const int z = blockIdx.z;
    const __half* A    = args.A[z];
    const __half* Wt   = args.W[z];
    const float*  bias = args.bias[z];
    void*         Y    = args.Y[z];
    const float alpha  = args.alpha[z];

    const int tid  = threadIdx.x;
    const int wid  = tid >> 5;
    const int lane = tid & 31;
    const int bm   = blockIdx.y * GBM;
    const int n0   = blockIdx.x * GBN;

    if (tid < GBN / 4)
        *(float4*)(bsm + tid * 4) = *(const float4*)(bias + n0 + tid * 4);

    auto loadA = [&](int slot, int kt) {
        const __half* src = A + (size_t)bm * C + kt * GBK;
        const uint32_t base = sA + slot * AST;
        #pragma unroll
        for (int c = 0; c < 4; c++) {
            const int ci = tid + c * 256;
            const int r = ci >> 3, g = ci & 7;
            CP_ASYNC16(base + r * 128 + ((g * 16) ^ ((r & 7) * 16)),
                       src + (size_t)r * C + g * 8);
        }
    };
    auto loadB = [&](int slot, int kt) {
        const __half* src = Wt + (size_t)n0 * C + kt * GBK;
        const uint32_t base = sB + slot * BST;
        #pragma unroll
        for (int c = 0; c < 4; c++) {
            const int ci = tid + c * 256;
            const int r = ci >> 3, g = ci & 7;
            CP_ASYNC16(base + r * 128 + ((g * 16) ^ ((r & 7) * 16)),
                       src + (size_t)r * C + g * 8);
        }
    };

    loadA(0, 0); loadB(0, 0); CP_COMMIT();
    loadA(1, 1); loadB(1, 1); CP_COMMIT();

    float acc[2][8][4];
    #pragma unroll
    for (int i = 0; i < 2; i++)
        #pragma unroll
        for (int j = 0; j < 8; j++)
            #pragma unroll
            for (int l = 0; l < 4; l++) acc[i][j][l] = 0.f;

    const int r8 = lane & 7;
    const int qa = lane >> 3;
    const int wm = (wid & 3) * 32;
    const int wn = (wid >> 2) * 64;
    const uint32_t a_rb   = (wm + (qa & 1) * 8 + r8) * 128;
    const uint32_t a_ksel = (uint32_t)(qa >> 1) * 16;
    const uint32_t b_rb   = (wn + (qa >> 1) * 8 + r8) * 128;
    const uint32_t b_ksel = (uint32_t)(qa & 1) * 16;
    const uint32_t xorp   = (uint32_t)r8 * 16;

    for (int kt = 0; kt < NKT; kt++) {
        if (kt < NKT - 2) { CP_WAIT(1); } else { CP_WAIT(0); }
        __syncthreads();
        if (kt + 2 < NKT) {
            const int s2 = (kt + 2) % 3;
            loadA(s2, kt + 2); loadB(s2, kt + 2); CP_COMMIT();
        }
        const int slot = kt % 3;
        const uint32_t aBase = sA + slot * AST + a_rb;
        const uint32_t bBase = sB + slot * BST + b_rb;

        #pragma unroll
        for (int ks = 0; ks < 4; ks++) {
            const uint32_t akoff = ((uint32_t)ks * 32 + a_ksel) ^ xorp;
            const uint32_t bkoff = ((uint32_t)ks * 32 + b_ksel) ^ xorp;
            uint32_t af[2][4], bf[4][4];
            #pragma unroll
            for (int mt = 0; mt < 2; mt++)
                LDSM_X4(af[mt], aBase + mt * (16 * 128) + akoff);
            #pragma unroll
            for (int p = 0; p < 4; p++)
                LDSM_X4(bf[p], bBase + p * (16 * 128) + bkoff);
            #pragma unroll
            for (int mt = 0; mt < 2; mt++)
                #pragma unroll
                for (int p = 0; p < 4; p++) {
                    MMA_F16(acc[mt][2 * p + 0], af[mt], bf[p][0], bf[p][1]);
                    MMA_F16(acc[mt][2 * p + 1], af[mt], bf[p][2], bf[p][3]);
                }
        }
    }
    __syncthreads();

    const int erow  = bm + wm + (lane >> 2);
    const int ecol0 = wn + 2 * (lane & 3);
    #pragma unroll
    for (int mt = 0; mt < 2; mt++) {
        #pragma unroll
        for (int nt = 0; nt < 8; nt++) {
            const int col = ecol0 + nt * 8;
            const float b0 = bsm[col], b1 = bsm[col + 1];
            const float x0 = alpha * (acc[mt][nt][0] + b0);
            const float x1 = alpha * (acc[mt][nt][1] + b1);
            const float x2 = alpha * (acc[mt][nt][2] + b0);
            const float x3 = alpha * (acc[mt][nt][3] + b1);
            if (HALF_OUT) {
                __half* Yh = (__half*)Y;
                *(__half2*)(Yh + (size_t)(erow + mt * 16)     * C + n0 + col) = __floats2half2_rn(x0, x1);
                *(__half2*)(Yh + (size_t)(erow + mt * 16 + 8) * C + n0 + col) = __floats2half2_rn(x2, x3);
            } else {
                float* Yf = (float*)Y;
                float2 lo; lo.x = x0; lo.y = x1;
                float2 hi; hi.x = x2; hi.y = x3;
                *(float2*)(Yf + (size_t)(erow + mt * 16)     * C + n0 + col) = lo;
                *(float2*)(Yf + (size_t)(erow + mt * 16 + 8) * C + n0 + col) = hi;
            }
        }
    }
}

// ---------------------------------------------------------------------------
// fp16 tensor-core block-local attention, 512 threads.
// QK: warp grid 4(m) x 4(k-groups) over 64x192. Register softmax with small
// cross-warp reduce buffers. PV: 4(m) x 4(d) over 64x64, K=192, V via
// ldmatrix.trans. Output written fp16 to g_a.
// ---------------------------------------------------------------------------
__global__ __launch_bounds__(ATHR, 1)
void attn_kernel(const __half* __restrict__ q, const __half* __restrict__ k,
                 const __half* __restrict__ v, __half* __restrict__ o)
{
    extern __shared__ char smem[];
    const uint32_t sb = smem_u32(smem);
    float* redA = (float*)(smem + SMRA);
    float* redB = (float*)(smem + SMRB);

    const int nb  = blockIdx.x;
    const int h   = blockIdx.y;
    const int b   = blockIdx.z;
    const int tid = threadIdx.x;
    const int wid  = tid >> 5;
    const int lane = tid & 31;
    const int start = nb * BS;
    const size_t rowBase = (size_t)b * T * C + (size_t)h * D;

    const __half* qp = q + rowBase;
    const __half* kp = k + rowBase;
    const __half* vp = v + rowBase;

    // --- cp.async: group0 = Q + K, group1 = V.  128B fp16 rows, swizzled. ---
    {
        {   // Q: 64 rows x 8 granules = 512
            const int r = tid >> 3, g = tid & 7;
            CP_ASYNC16(sb + SMQ + r * 128 + ((g * 16) ^ ((r & 7) * 16)),
                       qp + (size_t)(start + r) * C + g * 8);
        }
        #pragma unroll
        for (int i = 0; i < 3; i++) {   // K: 192 x 8 = 1536
            const int idx = tid + i * ATHR;
            const int r = idx >> 3, g = idx & 7;
            int p = start - LW / 2 + r;
            p = p < 0 ? 0 : (p >= T ? T - 1 : p);
            CP_ASYNC16(sb + SMK + r * 128 + ((g * 16) ^ ((r & 7) * 16)),
                       kp + (size_t)p * C + g * 8);
        }
        CP_COMMIT();
        #pragma unroll
        for (int i = 0; i < 3; i++) {   // V: 192 x 8
            const int idx = tid + i * ATHR;
            const int r = idx >> 3, g = idx & 7;
            int p = start - LW / 2 + r;
            p = p < 0 ? 0 : (p >= T ? T - 1 : p);
            CP_ASYNC16(sb + SMV + r * 128 + ((g * 16) ^ ((r & 7) * 16)),
                       vp + (size_t)p * C + g * 8);
        }
        CP_COMMIT();
    }

    const int r8 = lane & 7;
    const int qa = lane >> 3;
    const uint32_t xorp = (uint32_t)r8 * 16;
    const int kg = wid >> 2;                  // k-group (QK) / d-group (PV)

    // --- QK^T: warp tile 16 q-rows x 48 k-cols, D=64 = 4 k16 steps ---
    const int wmq = (wid & 3) * 16;
    const int wnq = kg * 48;
    const uint32_t aQ_rb = (wmq + (qa & 1) * 8 + r8) * 128;
    const uint32_t aQ_ks = (uint32_t)(qa >> 1) * 16;
    const uint32_t bK_rb = (wnq + (qa >> 1) * 8 + r8) * 128;
    const uint32_t bK_ks = (uint32_t)(qa & 1) * 16;

    float accS[6][4];
    #pragma unroll
    for (int i = 0; i < 6; i++)
        #pragma unroll
        for (int l = 0; l < 4; l++) accS[i][l] = 0.f;

    CP_WAIT(1);
    __syncthreads();

    #pragma unroll
    for (int ks = 0; ks < 4; ks++) {
        uint32_t af[4], bf[3][4];
        LDSM_X4(af, sb + SMQ + aQ_rb + (((uint32_t)ks * 32 + aQ_ks) ^ xorp));
        #pragma unroll
        for (int p = 0; p < 3; p++)
            LDSM_X4(bf[p], sb + SMK + bK_rb + p * (16 * 128) + (((uint32_t)ks * 32 + bK_ks) ^ xorp));
        #pragma unroll
        for (int p = 0; p < 3; p++) {
            MMA_F16(accS[2 * p + 0], af, bf[p][0], bf[p][1]);
            MMA_F16(accS[2 * p + 1], af, bf[p][2], bf[p][3]);
        }
    }

    // --- Register softmax over 192 cols (4 k-group warps per row set) ---
    const int r0 = wmq + (lane >> 2);
    const int r1 = r0 + 8;
    const int c0 = wnq + 2 * (lane & 3);

    // mask + per-thread max
    float mx0 = -INFINITY, mx1 = -INFINITY;
    #pragma unroll
    for (int nt = 0; nt < 6; nt++) {
        const int ca = c0 + nt * 8, cb = ca + 1;
        const int pa = start - LW / 2 + ca, pb = pa + 1;
        const bool va = (pa >= 0) & (pa < T);
        const bool vb = (pb >= 0) & (pb < T);
        if (!va) { accS[nt][0] = -INFINITY; accS[nt][2] = -INFINITY; }
        if (!vb) { accS[nt][1] = -INFINITY; accS[nt][3] = -INFINITY; }
        mx0 = fmaxf(mx0, fmaxf(accS[nt][0], accS[nt][1]));
        mx1 = fmaxf(mx1, fmaxf(accS[nt][2], accS[nt][3]));
    }
    // quad reduce (lanes sharing a row)
    #pragma unroll
    for (int off = 1; off <= 2; off <<= 1) {
        mx0 = fmaxf(mx0, __shfl_xor_sync(0xffffffffu, mx0, off));
        mx1 = fmaxf(mx1, __shfl_xor_sync(0xffffffffu, mx1, off));
    }
    if ((lane & 3) == 0) { redA[r0 * 4 + kg] = mx0; redA[r1 * 4 + kg] = mx1; }
    __syncthreads();
    mx0 = fmaxf(fmaxf(redA[r0 * 4 + 0], redA[r0 * 4 + 1]),
                fmaxf(redA[r0 * 4 + 2], redA[r0 * 4 + 3]));
    mx1 = fmaxf(fmaxf(redA[r1 * 4 + 0], redA[r1 * 4 + 1]),
                fmaxf(redA[r1 * 4 + 2], redA[r1 * 4 + 3]));

    // exp + per-thread sum
    float s0 = 0.f, s1 = 0.f;
    #pragma unroll
    for (int nt = 0; nt < 6; nt++) {
        accS[nt][0] = __expf(accS[nt][0] - mx0);
        accS[nt][1] = __expf(accS[nt][1] - mx0);
        accS[nt][2] = __expf(accS[nt][2] - mx1);
        accS[nt][3] = __expf(accS[nt][3] - mx1);
        s0 += accS[nt][0] + accS[nt][1];
        s1 += accS[nt][2] + accS[nt][3];
    }
    #pragma unroll
    for (int off = 1; off <= 2; off <<= 1) {
        s0 += __shfl_xor_sync(0xffffffffu, s0, off);
        s1 += __shfl_xor_sync(0xffffffffu, s1, off);
    }
    if ((lane & 3) == 0) { redB[r0 * 4 + kg] = s0; redB[r1 * 4 + kg] = s1; }
    CP_WAIT(0);              // V resident before PV
    __syncthreads();
    const float inv0 = 1.f / (redB[r0 * 4 + 0] + redB[r0 * 4 + 1] +
                              redB[r0 * 4 + 2] + redB[r0 * 4 + 3]);
    const float inv1 = 1.f / (redB[r1 * 4 + 0] + redB[r1 * 4 + 1] +
                              redB[r1 * 4 + 2] + redB[r1 * 4 + 3]);

    // write P (fp16) into swizzled k64-panels
    #pragma unroll
    for (int nt = 0; nt < 6; nt++) {
        const int c = c0 + nt * 8;
        const int pan = c >> 6, cc = (c & 63) * 2;
        const uint32_t a0 = sb + SMP + pan * 8192 + r0 * 128 + (cc ^ ((r0 & 7) * 16));
        const uint32_t a1 = sb + SMP + pan * 8192 + r1 * 128 + (cc ^ ((r1 & 7) * 16));
        __half2 h0 = __floats2half2_rn(accS[nt][0] * inv0, accS[nt][1] * inv0);
        __half2 h1 = __floats2half2_rn(accS[nt][2] * inv1, accS[nt][3] * inv1);
        *(__half2*)(smem + (a0 - sb)) = h0;
        *(__half2*)(smem + (a1 - sb)) = h1;
    }
    __syncthreads();

    // --- P @ V: warp tile 16 q-rows x 16 d-cols, K=192 = 12 k16 steps ---
    const int wmp = (wid & 3) * 16;
    const int wnp = kg * 16;
    const uint32_t aP_rb = (wmp + (qa & 1) * 8 + r8) * 128;
    const uint32_t aP_ks = (uint32_t)(qa >> 1) * 16;
    const uint32_t v_row = (qa & 1) * 8 + r8;
    const uint32_t v_doff = ((uint32_t)wnp * 2 + (uint32_t)(qa >> 1) * 16) ^ xorp;

    float accO[2][4];
    #pragma unroll
    for (int i = 0; i < 2; i++)
        #pragma unroll
        for (int l = 0; l < 4; l++) accO[i][l] = 0.f;

    #pragma unroll
    for (int pan = 0; pan < 3; pan++) {
        #pragma unroll
        for (int ks = 0; ks < 4; ks++) {
            uint32_t af[4], bf[4];
            LDSM_X4(af, sb + SMP + pan * 8192 + aP_rb + (((uint32_t)ks * 32 + aP_ks) ^ xorp));
            LDSM_X4_T(bf, sb + SMV + (pan * 64 + ks * 16 + v_row) * 128 + v_doff);
            MMA_F16(accO[0], af, bf[0], bf[1]);
            MMA_F16(accO[1], af, bf[2], bf[3]);
        }
    }

    // write O (fp16)
    {
        const int orow = wmp + (lane >> 2);
        const int oc0  = wnp + 2 * (lane & 3);
        #pragma unroll
        for (int nt = 0; nt < 2; nt++) {
            const int c = oc0 + nt * 8;
            *(__half2*)(o + rowBase + (size_t)(start + orow) * C + c) =
                __floats2half2_rn(accO[nt][0], accO[nt][1]);
            *(__half2*)(o + rowBase + (size_t)(start + orow + 8) * C + c) =
                __floats2half2_rn(accO[nt][2], accO[nt][3]);
        }
    }
}

// ---------------------------------------------------------------------------
extern "C" void kernel_launch(void* const* d_in, const int* in_sizes, int n_in,
                              void* d_out, int out_size)
{
    const float* query = (const float*)d_in[0];
    const float* key   = (const float*)d_in[1];
    const float* value = (const float*)d_in[2];
    const float* Wq    = (const float*)d_in[3];
    const float* bq    = (const float*)d_in[4];
    const float* Wk    = (const float*)d_in[5];
    const float* bk    = (const float*)d_in[6];
    const float* Wv    = (const float*)d_in[7];
    const float* bv    = (const float*)d_in[8];
    const float* Wo    = (const float*)d_in[9];
    const float* bo    = (const float*)d_in[10];
    float* out = (float*)d_out;

    __half *gq, *gk, *gv, *ga, *gx, *gw;
    cudaGetSymbolAddress((void**)&gq, g_q);
    cudaGetSymbolAddress((void**)&gk, g_k);
    cudaGetSymbolAddress((void**)&gv, g_v);
    cudaGetSymbolAddress((void**)&ga, g_a);
    cudaGetSymbolAddress((void**)&gx, g_x16);
    cudaGetSymbolAddress((void**)&gw, g_w16);
    const __half* x0 = gx;
    const __half* x1 = gx + (size_t)M * C;
    const __half* x2 = gx + (size_t)2 * M * C;
    const __half* w0 = gw;
    const __half* w1 = gw + (size_t)C * C;
    const __half* w2 = gw + (size_t)2 * C * C;
    const __half* w3 = gw + (size_t)3 * C * C;

    cudaFuncSetAttribute(gemm_mma<true>,
                         cudaFuncAttributeMaxDynamicSharedMemorySize, SM_GEMM);
    cudaFuncSetAttribute(gemm_mma<false>,
                         cudaFuncAttributeMaxDynamicSharedMemorySize, SM_GEMM);
    cudaFuncSetAttribute(attn_kernel,
                         cudaFuncAttributeMaxDynamicSharedMemorySize, SMEM_ATTN);

    conv_act<<<(3 * M * (C / 4)) / 256, 256>>>(
        (const float4*)query, (const float4*)key, (const float4*)value);
    conv_weights<<<(4 * C * (C / 4)) / 256, 256>>>(
        (const float4*)Wq, (const float4*)Wk, (const float4*)Wv, (const float4*)Wo);

    const float scale = 0.125f;   // 64^-0.5

    GemmArgs qkv;
    qkv.A[0] = x0; qkv.A[1] = x1; qkv.A[2] = x2;
    qkv.W[0] = w0; qkv.W[1] = w1; qkv.W[2] = w2;
    qkv.bias[0] = bq; qkv.bias[1] = bk; qkv.bias[2] = bv;
    qkv.Y[0] = gq; qkv.Y[1] = gk; qkv.Y[2] = gv;
    qkv.alpha[0] = scale; qkv.alpha[1] = 1.0f; qkv.alpha[2] = 1.0f;
    gemm_mma<true><<<dim3(C / GBN, M / GBM, 3), 256, SM_GEMM>>>(qkv);

    attn_kernel<<<dim3(NB, H, B), ATHR, SMEM_ATTN>>>(gq, gk, gv, ga);

    GemmArgs og;
    og.A[0] = ga; og.A[1] = ga; og.A[2] = ga;
    og.W[0] = w3; og.W[1] = w3; og.W[2] = w3;
    og.bias[0] = bo; og.bias[1] = bo; og.bias[2] = bo;
    og.Y[0] = out; og.Y[1] = out; og.Y[2] = out;
    og.alpha[0] = 1.0f; og.alpha[1] = 1.0f; og.alpha[2] = 1.0f;
    gemm_mma<false><<<dim3(C / GBN, M / GBM, 1), 256, SM_GEMM>>>(og);
}

// round 8
// speedup vs baseline: 7.9165x; 1.0734x over previous
#include <cuda_runtime.h>
#include <cuda_fp16.h>
#include <math.h>
#include <cstdint>

// ---------------------------------------------------------------------------
// Problem constants
// ---------------------------------------------------------------------------
constexpr int B  = 2;
constexpr int T  = 8192;
constexpr int C  = 1024;
constexpr int H  = 16;
constexpr int BS = 64;
constexpr int LW = 128;
constexpr int D  = 64;
constexpr int WN = BS + LW;     // 192
constexpr int NB = T / BS;      // 128
constexpr int M  = B * T;       // 16384

// ---------------------------------------------------------------------------
// GEMM config: mma.sync m16n8k16 fp16, CTA tile 128x128x64, 8 warps (32x64),
// 3-stage cp.async pipeline, 2 CTAs/SM.
// ---------------------------------------------------------------------------
constexpr int GBM = 128;
constexpr int GBN = 128;
constexpr int GBK = 64;                       // 64 fp16 = 128B rows
constexpr int NKT = C / GBK;                  // 16
constexpr int AST = GBM * GBK * 2;            // 16384 B
constexpr int BST = GBN * GBK * 2;            // 16384 B
constexpr int SM_B_OFF = 3 * AST;             // 49152
constexpr int SM_BIAS  = 3 * AST + 3 * BST;   // 98304
constexpr int SM_GEMM  = SM_BIAS + GBN * 4;   // 98816

// ---------------------------------------------------------------------------
// Attention smem layout (bytes), fp16 tiles, 128B rows.
// P panels (24KB) OVERLAY the dead Q+K region (32KB) after QK completes.
// ---------------------------------------------------------------------------
constexpr int SMQ   = 0;        // 64 x 128B  = 8KB
constexpr int SMK   = 8192;     // 192 x 128B = 24KB
constexpr int SMV   = 32768;    // 192 x 128B = 24KB
constexpr int SMP   = 0;        // 3 panels x 64 x 128B = 24KB (overlays Q+K)
constexpr int SMRA  = 57344;    // 64 x 4 f32 (max reduce)
constexpr int SMRB  = 58368;    // 64 x 4 f32 (sum reduce)
constexpr int SMEM_ATTN = 59392;
constexpr int ATHR = 512;

// ---------------------------------------------------------------------------
// Scratch
// ---------------------------------------------------------------------------
__device__ __align__(16) __half g_x16[3][(size_t)M * C];   // fp16 inputs
__device__ __align__(16) __half g_w16[4][(size_t)C * C];   // fp16 weights
__device__ __align__(16) __half g_q[(size_t)M * C];
__device__ __align__(16) __half g_k[(size_t)M * C];
__device__ __align__(16) __half g_v[(size_t)M * C];
__device__ __align__(16) __half g_a[(size_t)M * C];

struct GemmArgs {
    const __half* A[3];
    const __half* W[3];
    const float*  bias[3];
    void*         Y[3];
    float         alpha[3];
};

// ---------------------------------------------------------------------------
// PTX helpers (base sm_103-safe)
// ---------------------------------------------------------------------------
__device__ __forceinline__ uint32_t smem_u32(const void* p) {
    uint32_t a;
    asm("{ .reg .u64 t; cvta.to.shared.u64 t, %1; cvt.u32.u64 %0, t; }" : "=r"(a) : "l"(p));
    return a;
}

#define CP_ASYNC16(dst, src) \
    asm volatile("cp.async.cg.shared.global [%0], [%1], 16;" :: "r"(dst), "l"(src) : "memory")
#define CP_COMMIT() asm volatile("cp.async.commit_group;" ::: "memory")
#define CP_WAIT(n)  asm volatile("cp.async.wait_group %0;" :: "n"(n) : "memory")

#define LDSM_X4(r, addr) \
    asm volatile("ldmatrix.sync.aligned.m8n8.x4.shared.b16 {%0,%1,%2,%3}, [%4];" \
        : "=r"((r)[0]), "=r"((r)[1]), "=r"((r)[2]), "=r"((r)[3]) : "r"(addr))

#define LDSM_X4_T(r, addr) \
    asm volatile("ldmatrix.sync.aligned.m8n8.x4.trans.shared.b16 {%0,%1,%2,%3}, [%4];" \
        : "=r"((r)[0]), "=r"((r)[1]), "=r"((r)[2]), "=r"((r)[3]) : "r"(addr))

#define MMA_F16(d, a, b0, b1) \
    asm volatile("mma.sync.aligned.m16n8k16.row.col.f32.f16.f16.f32 " \
        "{%0,%1,%2,%3}, {%4,%5,%6,%7}, {%8,%9}, {%0,%1,%2,%3};" \
        : "+f"((d)[0]), "+f"((d)[1]), "+f"((d)[2]), "+f"((d)[3]) \
        : "r"((a)[0]), "r"((a)[1]), "r"((a)[2]), "r"((a)[3]), "r"(b0), "r"(b1))

// ---------------------------------------------------------------------------
// Prepass: all fp32 -> fp16 conversions in ONE launch.
// ---------------------------------------------------------------------------
constexpr size_t PER4A = (size_t)M * C / 4;   // 4194304 float4 per activation
constexpr size_t PER4W = (size_t)C * C / 4;   // 262144 float4 per weight
constexpr size_t CONV_TOTAL = 3 * PER4A + 4 * PER4W;

__global__ __launch_bounds__(256)
void conv_all(const float4* __restrict__ q, const float4* __restrict__ k,
              const float4* __restrict__ v,
              const float4* __restrict__ w0, const float4* __restrict__ w1,
              const float4* __restrict__ w2, const float4* __restrict__ w3)
{
    size_t i = (size_t)blockIdx.x * 256 + threadIdx.x;
    const float4* src;
    __half2* dst;
    if (i < 3 * PER4A) {
        const int which = (int)(i / PER4A);
        const size_t off = i - (size_t)which * PER4A;
        src = (which == 0 ? q : which == 1 ? k : v) + off;
        dst = (__half2*)&g_x16[which][off * 4];
    } else {
        i -= 3 * PER4A;
        const int which = (int)(i / PER4W);
        const size_t off = i - (size_t)which * PER4W;
        src = (which == 0 ? w0 : which == 1 ? w1 : which == 2 ? w2 : w3) + off;
        dst = (__half2*)&g_w16[which][off * 4];
    }
    float4 x = *src;
    dst[0] = __floats2half2_rn(x.x, x.y);
    dst[1] = __floats2half2_rn(x.z, x.w);
}

// ---------------------------------------------------------------------------
// fp16 GEMM: Y[m,n] = alpha * (sum_k A[m,k] * W[n,k] + bias[n])
// ---------------------------------------------------------------------------
template <bool HALF_OUT>
__global__ __launch_bounds__(256, 2)
void gemm_mma(const GemmArgs args)
{
    extern __shared__ char smem[];
    const uint32_t sA = smem_u32(smem);
    const uint32_t sB = sA + SM_B_OFF;
    float* bsm = (float*)(smem + SM_BIAS);

    const int z = blockIdx.z;
    const __half* A    = args.A[z];
    const __half* Wt   = args.W[z];
    const float*  bias = args.bias[z];
    void*         Y    = args.Y[z];
    const float alpha  = args.alpha[z];

    const int tid  = threadIdx.x;
    const int wid  = tid >> 5;
    const int lane = tid & 31;
    const int bm   = blockIdx.y * GBM;
    const int n0   = blockIdx.x * GBN;

    if (tid < GBN / 4)
        *(float4*)(bsm + tid * 4) = *(const float4*)(bias + n0 + tid * 4);

    auto loadA = [&](int slot, int kt) {
        const __half* src = A + (size_t)bm * C + kt * GBK;
        const uint32_t base = sA + slot * AST;
        #pragma unroll
        for (int c = 0; c < 4; c++) {
            const int ci = tid + c * 256;
            const int r = ci >> 3, g = ci & 7;
            CP_ASYNC16(base + r * 128 + ((g * 16) ^ ((r & 7) * 16)),
                       src + (size_t)r * C + g * 8);
        }
    };
    auto loadB = [&](int slot, int kt) {
        const __half* src = Wt + (size_t)n0 * C + kt * GBK;
        const uint32_t base = sB + slot * BST;
        #pragma unroll
        for (int c = 0; c < 4; c++) {
            const int ci = tid + c * 256;
            const int r = ci >> 3, g = ci & 7;
            CP_ASYNC16(base + r * 128 + ((g * 16) ^ ((r & 7) * 16)),
                       src + (size_t)r * C + g * 8);
        }
    };

    loadA(0, 0); loadB(0, 0); CP_COMMIT();
    loadA(1, 1); loadB(1, 1); CP_COMMIT();

    float acc[2][8][4];
    #pragma unroll
    for (int i = 0; i < 2; i++)
        #pragma unroll
        for (int j = 0; j < 8; j++)
            #pragma unroll
            for (int l = 0; l < 4; l++) acc[i][j][l] = 0.f;

    const int r8 = lane & 7;
    const int qa = lane >> 3;
    const int wm = (wid & 3) * 32;
    const int wn = (wid >> 2) * 64;
    const uint32_t a_rb   = (wm + (qa & 1) * 8 + r8) * 128;
    const uint32_t a_ksel = (uint32_t)(qa >> 1) * 16;
    const uint32_t b_rb   = (wn + (qa >> 1) * 8 + r8) * 128;
    const uint32_t b_ksel = (uint32_t)(qa & 1) * 16;
    const uint32_t xorp   = (uint32_t)r8 * 16;

    for (int kt = 0; kt < NKT; kt++) {
        if (kt < NKT - 2) { CP_WAIT(1); } else { CP_WAIT(0); }
        __syncthreads();
        if (kt + 2 < NKT) {
            const int s2 = (kt + 2) % 3;
            loadA(s2, kt + 2); loadB(s2, kt + 2); CP_COMMIT();
        }
        const int slot = kt % 3;
        const uint32_t aBase = sA + slot * AST + a_rb;
        const uint32_t bBase = sB + slot * BST + b_rb;

        #pragma unroll
        for (int ks = 0; ks < 4; ks++) {
            const uint32_t akoff = ((uint32_t)ks * 32 + a_ksel) ^ xorp;
            const uint32_t bkoff = ((uint32_t)ks * 32 + b_ksel) ^ xorp;
            uint32_t af[2][4], bf[4][4];
            #pragma unroll
            for (int mt = 0; mt < 2; mt++)
                LDSM_X4(af[mt], aBase + mt * (16 * 128) + akoff);
            #pragma unroll
            for (int p = 0; p < 4; p++)
                LDSM_X4(bf[p], bBase + p * (16 * 128) + bkoff);
            #pragma unroll
            for (int mt = 0; mt < 2; mt++)
                #pragma unroll
                for (int p = 0; p < 4; p++) {
                    MMA_F16(acc[mt][2 * p + 0], af[mt], bf[p][0], bf[p][1]);
                    MMA_F16(acc[mt][2 * p + 1], af[mt], bf[p][2], bf[p][3]);
                }
        }
    }
    __syncthreads();

    const int erow  = bm + wm + (lane >> 2);
    const int ecol0 = wn + 2 * (lane & 3);
    #pragma unroll
    for (int mt = 0; mt < 2; mt++) {
        #pragma unroll
        for (int nt = 0; nt < 8; nt++) {
            const int col = ecol0 + nt * 8;
            const float b0 = bsm[col], b1 = bsm[col + 1];
            const float x0 = alpha * (acc[mt][nt][0] + b0);
            const float x1 = alpha * (acc[mt][nt][1] + b1);
            const float x2 = alpha * (acc[mt][nt][2] + b0);
            const float x3 = alpha * (acc[mt][nt][3] + b1);
            if (HALF_OUT) {
                __half* Yh = (__half*)Y;
                *(__half2*)(Yh + (size_t)(erow + mt * 16)     * C + n0 + col) = __floats2half2_rn(x0, x1);
                *(__half2*)(Yh + (size_t)(erow + mt * 16 + 8) * C + n0 + col) = __floats2half2_rn(x2, x3);
            } else {
                float* Yf = (float*)Y;
                float2 lo; lo.x = x0; lo.y = x1;
                float2 hi; hi.x = x2; hi.y = x3;
                *(float2*)(Yf + (size_t)(erow + mt * 16)     * C + n0 + col) = lo;
                *(float2*)(Yf + (size_t)(erow + mt * 16 + 8) * C + n0 + col) = hi;
            }
        }
    }
}

// ---------------------------------------------------------------------------
// fp16 tensor-core block-local attention, 512 threads, 2 CTAs/SM.
// P panels overlay the dead Q+K region after QK completes.
// ---------------------------------------------------------------------------
__global__ __launch_bounds__(ATHR, 2)
void attn_kernel(const __half* __restrict__ q, const __half* __restrict__ k,
                 const __half* __restrict__ v, __half* __restrict__ o)
{
    extern __shared__ char smem[];
    const uint32_t sb = smem_u32(smem);
    float* redA = (float*)(smem + SMRA);
    float* redB = (float*)(smem + SMRB);

    const int nb  = blockIdx.x;
    const int h   = blockIdx.y;
    const int b   = blockIdx.z;
    const int tid = threadIdx.x;
    const int wid  = tid >> 5;
    const int lane = tid & 31;
    const int start = nb * BS;
    const size_t rowBase = (size_t)b * T * C + (size_t)h * D;

    const __half* qp = q + rowBase;
    const __half* kp = k + rowBase;
    const __half* vp = v + rowBase;

    // --- cp.async: group0 = Q + K, group1 = V. 128B fp16 rows, swizzled. ---
    {
        {   // Q: 64 rows x 8 granules = 512
            const int r = tid >> 3, g = tid & 7;
            CP_ASYNC16(sb + SMQ + r * 128 + ((g * 16) ^ ((r & 7) * 16)),
                       qp + (size_t)(start + r) * C + g * 8);
        }
        #pragma unroll
        for (int i = 0; i < 3; i++) {   // K: 192 x 8 = 1536
            const int idx = tid + i * ATHR;
            const int r = idx >> 3, g = idx & 7;
            int p = start - LW / 2 + r;
            p = p < 0 ? 0 : (p >= T ? T - 1 : p);
            CP_ASYNC16(sb + SMK + r * 128 + ((g * 16) ^ ((r & 7) * 16)),
                       kp + (size_t)p * C + g * 8);
        }
        CP_COMMIT();
        #pragma unroll
        for (int i = 0; i < 3; i++) {   // V: 192 x 8
            const int idx = tid + i * ATHR;
            const int r = idx >> 3, g = idx & 7;
            int p = start - LW / 2 + r;
            p = p < 0 ? 0 : (p >= T ? T - 1 : p);
            CP_ASYNC16(sb + SMV + r * 128 + ((g * 16) ^ ((r & 7) * 16)),
                       vp + (size_t)p * C + g * 8);
        }
        CP_COMMIT();
    }

    const int r8 = lane & 7;
    const int qa = lane >> 3;
    const uint32_t xorp = (uint32_t)r8 * 16;
    const int kg = wid >> 2;                  // k-group (QK) / d-group (PV)

    // --- QK^T: warp tile 16 q-rows x 48 k-cols, D=64 = 4 k16 steps ---
    const int wmq = (wid & 3) * 16;
    const int wnq = kg * 48;
    const uint32_t aQ_rb = (wmq + (qa & 1) * 8 + r8) * 128;
    const uint32_t aQ_ks = (uint32_t)(qa >> 1) * 16;
    const uint32_t bK_rb = (wnq + (qa >> 1) * 8 + r8) * 128;
    const uint32_t bK_ks = (uint32_t)(qa & 1) * 16;

    float accS[6][4];
    #pragma unroll
    for (int i = 0; i < 6; i++)
        #pragma unroll
        for (int l = 0; l < 4; l++) accS[i][l] = 0.f;

    CP_WAIT(1);
    __syncthreads();

    #pragma unroll
    for (int ks = 0; ks < 4; ks++) {
        uint32_t af[4], bf[3][4];
        LDSM_X4(af, sb + SMQ + aQ_rb + (((uint32_t)ks * 32 + aQ_ks) ^ xorp));
        #pragma unroll
        for (int p = 0; p < 3; p++)
            LDSM_X4(bf[p], sb + SMK + bK_rb + p * (16 * 128) + (((uint32_t)ks * 32 + bK_ks) ^ xorp));
        #pragma unroll
        for (int p = 0; p < 3; p++) {
            MMA_F16(accS[2 * p + 0], af, bf[p][0], bf[p][1]);
            MMA_F16(accS[2 * p + 1], af, bf[p][2], bf[p][3]);
        }
    }

    // --- Register softmax over 192 cols (4 k-group warps per row set) ---
    const int r0 = wmq + (lane >> 2);
    const int r1 = r0 + 8;
    const int c0 = wnq + 2 * (lane & 3);

    float mx0 = -INFINITY, mx1 = -INFINITY;
    #pragma unroll
    for (int nt = 0; nt < 6; nt++) {
        const int ca = c0 + nt * 8, cb = ca + 1;
        const int pa = start - LW / 2 + ca, pb = pa + 1;
        const bool va = (pa >= 0) & (pa < T);
        const bool vb = (pb >= 0) & (pb < T);
        if (!va) { accS[nt][0] = -INFINITY; accS[nt][2] = -INFINITY; }
        if (!vb) { accS[nt][1] = -INFINITY; accS[nt][3] = -INFINITY; }
        mx0 = fmaxf(mx0, fmaxf(accS[nt][0], accS[nt][1]));
        mx1 = fmaxf(mx1, fmaxf(accS[nt][2], accS[nt][3]));
    }
    #pragma unroll
    for (int off = 1; off <= 2; off <<= 1) {
        mx0 = fmaxf(mx0, __shfl_xor_sync(0xffffffffu, mx0, off));
        mx1 = fmaxf(mx1, __shfl_xor_sync(0xffffffffu, mx1, off));
    }
    if ((lane & 3) == 0) { redA[r0 * 4 + kg] = mx0; redA[r1 * 4 + kg] = mx1; }
    __syncthreads();   // also: all QK smem reads complete before this point
    mx0 = fmaxf(fmaxf(redA[r0 * 4 + 0], redA[r0 * 4 + 1]),
                fmaxf(redA[r0 * 4 + 2], redA[r0 * 4 + 3]));
    mx1 = fmaxf(fmaxf(redA[r1 * 4 + 0], redA[r1 * 4 + 1]),
                fmaxf(redA[r1 * 4 + 2], redA[r1 * 4 + 3]));

    float s0 = 0.f, s1 = 0.f;
    #pragma unroll
    for (int nt = 0; nt < 6; nt++) {
        accS[nt][0] = __expf(accS[nt][0] - mx0);
        accS[nt][1] = __expf(accS[nt][1] - mx0);
        accS[nt][2] = __expf(accS[nt][2] - mx1);
        accS[nt][3] = __expf(accS[nt][3] - mx1);
        s0 += accS[nt][0] + accS[nt][1];
        s1 += accS[nt][2] + accS[nt][3];
    }
    #pragma unroll
    for (int off = 1; off <= 2; off <<= 1) {
        s0 += __shfl_xor_sync(0xffffffffu, s0, off);
        s1 += __shfl_xor_sync(0xffffffffu, s1, off);
    }
    if ((lane & 3) == 0) { redB[r0 * 4 + kg] = s0; redB[r1 * 4 + kg] = s1; }
    CP_WAIT(0);              // V resident before PV
    __syncthreads();         // after this, Q+K region is dead -> P overlay safe
    const float inv0 = 1.f / (redB[r0 * 4 + 0] + redB[r0 * 4 + 1] +
                              redB[r0 * 4 + 2] + redB[r0 * 4 + 3]);
    const float inv1 = 1.f / (redB[r1 * 4 + 0] + redB[r1 * 4 + 1] +
                              redB[r1 * 4 + 2] + redB[r1 * 4 + 3]);

    // write P (fp16) into swizzled k64-panels (overlaying Q+K)
    #pragma unroll
    for (int nt = 0; nt < 6; nt++) {
        const int c = c0 + nt * 8;
        const int pan = c >> 6, cc = (c & 63) * 2;
        const uint32_t o0 = SMP + pan * 8192 + r0 * 128 + (cc ^ ((r0 & 7) * 16));
        const uint32_t o1 = SMP + pan * 8192 + r1 * 128 + (cc ^ ((r1 & 7) * 16));
        *(__half2*)(smem + o0) = __floats2half2_rn(accS[nt][0] * inv0, accS[nt][1] * inv0);
        *(__half2*)(smem + o1) = __floats2half2_rn(accS[nt][2] * inv1, accS[nt][3] * inv1);
    }
    __syncthreads();

    // --- P @ V: warp tile 16 q-rows x 16 d-cols, K=192 = 12 k16 steps ---
    const int wmp = (wid & 3) * 16;
    const int wnp = kg * 16;
    const uint32_t aP_rb = (wmp + (qa & 1) * 8 + r8) * 128;
    const uint32_t aP_ks = (uint32_t)(qa >> 1) * 16;
    const uint32_t v_row = (qa & 1) * 8 + r8;
    const uint32_t v_doff = ((uint32_t)wnp * 2 + (uint32_t)(qa >> 1) * 16) ^ xorp;

    float accO[2][4];
    #pragma unroll
    for (int i = 0; i < 2; i++)
        #pragma unroll
        for (int l = 0; l < 4; l++) accO[i][l] = 0.f;

    #pragma unroll
    for (int pan = 0; pan < 3; pan++) {
        #pragma unroll
        for (int ks = 0; ks < 4; ks++) {
            uint32_t af[4], bf[4];
            LDSM_X4(af, sb + SMP + pan * 8192 + aP_rb + (((uint32_t)ks * 32 + aP_ks) ^ xorp));
            LDSM_X4_T(bf, sb + SMV + (pan * 64 + ks * 16 + v_row) * 128 + v_doff);
            MMA_F16(accO[0], af, bf[0], bf[1]);
            MMA_F16(accO[1], af, bf[2], bf[3]);
        }
    }

    // write O (fp16)
    {
        const int orow = wmp + (lane >> 2);
        const int oc0  = wnp + 2 * (lane & 3);
        #pragma unroll
        for (int nt = 0; nt < 2; nt++) {
            const int c = oc0 + nt * 8;
            *(__half2*)(o + rowBase + (size_t)(start + orow) * C + c) =
                __floats2half2_rn(accO[nt][0], accO[nt][1]);
            *(__half2*)(o + rowBase + (size_t)(start + orow + 8) * C + c) =
                __floats2half2_rn(accO[nt][2], accO[nt][3]);
        }
    }
}

// ---------------------------------------------------------------------------
extern "C" void kernel_launch(void* const* d_in, const int* in_sizes, int n_in,
                              void* d_out, int out_size)
{
    const float* query = (const float*)d_in[0];
    const float* key   = (const float*)d_in[1];
    const float* value = (const float*)d_in[2];
    const float* Wq    = (const float*)d_in[3];
    const float* bq    = (const float*)d_in[4];
    const float* Wk    = (const float*)d_in[5];
    const float* bk    = (const float*)d_in[6];
    const float* Wv    = (const float*)d_in[7];
    const float* bv    = (const float*)d_in[8];
    const float* Wo    = (const float*)d_in[9];
    const float* bo    = (const float*)d_in[10];
    float* out = (float*)d_out;

    __half *gq, *gk, *gv, *ga, *gx, *gw;
    cudaGetSymbolAddress((void**)&gq, g_q);
    cudaGetSymbolAddress((void**)&gk, g_k);
    cudaGetSymbolAddress((void**)&gv, g_v);
    cudaGetSymbolAddress((void**)&ga, g_a);
    cudaGetSymbolAddress((void**)&gx, g_x16);
    cudaGetSymbolAddress((void**)&gw, g_w16);
    const __half* x0 = gx;
    const __half* x1 = gx + (size_t)M * C;
    const __half* x2 = gx + (size_t)2 * M * C;
    const __half* w0 = gw;
    const __half* w1 = gw + (size_t)C * C;
    const __half* w2 = gw + (size_t)2 * C * C;
    const __half* w3 = gw + (size_t)3 * C * C;

    cudaFuncSetAttribute(gemm_mma<true>,
                         cudaFuncAttributeMaxDynamicSharedMemorySize, SM_GEMM);
    cudaFuncSetAttribute(gemm_mma<false>,
                         cudaFuncAttributeMaxDynamicSharedMemorySize, SM_GEMM);
    cudaFuncSetAttribute(attn_kernel,
                         cudaFuncAttributeMaxDynamicSharedMemorySize, SMEM_ATTN);

    conv_all<<<(int)(CONV_TOTAL / 256), 256>>>(
        (const float4*)query, (const float4*)key, (const float4*)value,
        (const float4*)Wq, (const float4*)Wk, (const float4*)Wv, (const float4*)Wo);

    const float scale = 0.125f;   // 64^-0.5

    GemmArgs qkv;
    qkv.A[0] = x0; qkv.A[1] = x1; qkv.A[2] = x2;
    qkv.W[0] = w0; qkv.W[1] = w1; qkv.W[2] = w2;
    qkv.bias[0] = bq; qkv.bias[1] = bk; qkv.bias[2] = bv;
    qkv.Y[0] = gq; qkv.Y[1] = gk; qkv.Y[2] = gv;
    qkv.alpha[0] = scale; qkv.alpha[1] = 1.0f; qkv.alpha[2] = 1.0f;
    gemm_mma<true><<<dim3(C / GBN, M / GBM, 3), 256, SM_GEMM>>>(qkv);

    attn_kernel<<<dim3(NB, H, B), ATHR, SMEM_ATTN>>>(gq, gk, gv, ga);

    GemmArgs og;
    og.A[0] = ga; og.A[1] = ga; og.A[2] = ga;
    og.W[0] = w3; og.W[1] = w3; og.W[2] = w3;
    og.bias[0] = bo; og.bias[1] = bo; og.bias[2] = bo;
    og.Y[0] = out; og.Y[1] = out; og.Y[2] = out;
    og.alpha[0] = 1.0f; og.alpha[1] = 1.0f; og.alpha[2] = 1.0f;
    gemm_mma<false><<<dim3(C / GBN, M / GBM, 1), 256, SM_GEMM>>>(og);
}